// round 1
// baseline (speedup 1.0000x reference)
#include <cuda_runtime.h>
#include <math.h>

// ---------------- problem constants ----------------
#define NL    6
#define DMODEL 1024
#define DFF   4096
#define VOC   32000
#define NH    16
#define HDIM  64
#define BATCH 2
#define TSEQ  1024
#define MTOK  (BATCH*TSEQ)   // 2048

// ---------------- scratch (static device globals; no allocation) ----------------
__device__ float g_x   [MTOK * DMODEL];
__device__ float g_h   [MTOK * DMODEL];
__device__ float g_qkv [MTOK * 3 * DMODEL];
__device__ float g_attn[(size_t)BATCH * NH * TSEQ * TSEQ];  // 134 MB
__device__ float g_o   [MTOK * DMODEL];
__device__ float g_ffn [(size_t)MTOK * DFF];

// ---------------- generic NT SGEMM: C[M,N] (op)= A[M,K] * B[N,K]^T ----------------
// 128x128 tile, BK=8, 256 threads, 8x8 per thread, k-major smem tiles.
// EPI: 0 = store, 1 = C += acc (residual), 2 = C = gelu(acc)
template<int EPI>
__global__ __launch_bounds__(256) void gemm_nt(
    const float* __restrict__ A, const float* __restrict__ B, float* __restrict__ C,
    int M, int N, int K, int lda, int ldb, int ldc)
{
    __shared__ float As[8][128];
    __shared__ float Bs[8][128];
    const int tid = threadIdx.x;
    const int tx = tid & 15;
    const int ty = tid >> 4;
    const int bm = blockIdx.y * 128;
    const int bn = blockIdx.x * 128;
    const int lrow = tid >> 1;          // 0..127
    const int lk   = (tid & 1) * 4;     // 0 or 4

    const float* Aptr = A + (size_t)(bm + lrow) * lda + lk;
    const float* Bptr = B + (size_t)(bn + lrow) * ldb + lk;

    float acc[8][8];
#pragma unroll
    for (int i = 0; i < 8; i++)
#pragma unroll
        for (int j = 0; j < 8; j++) acc[i][j] = 0.f;

    for (int k0 = 0; k0 < K; k0 += 8) {
        float4 a4 = *(const float4*)(Aptr + k0);
        float4 b4 = *(const float4*)(Bptr + k0);
        As[lk+0][lrow] = a4.x; As[lk+1][lrow] = a4.y;
        As[lk+2][lrow] = a4.z; As[lk+3][lrow] = a4.w;
        Bs[lk+0][lrow] = b4.x; Bs[lk+1][lrow] = b4.y;
        Bs[lk+2][lrow] = b4.z; Bs[lk+3][lrow] = b4.w;
        __syncthreads();
#pragma unroll
        for (int kk = 0; kk < 8; kk++) {
            float ra[8], rb[8];
            *(float4*)(ra)     = *(const float4*)&As[kk][ty*8];
            *(float4*)(ra + 4) = *(const float4*)&As[kk][ty*8 + 4];
            *(float4*)(rb)     = *(const float4*)&Bs[kk][tx*8];
            *(float4*)(rb + 4) = *(const float4*)&Bs[kk][tx*8 + 4];
#pragma unroll
            for (int i = 0; i < 8; i++)
#pragma unroll
                for (int j = 0; j < 8; j++)
                    acc[i][j] = fmaf(ra[i], rb[j], acc[i][j]);
        }
        __syncthreads();
    }

#pragma unroll
    for (int i = 0; i < 8; i++) {
        int row = bm + ty*8 + i;
        float* Crow = C + (size_t)row * ldc + bn + tx*8;
#pragma unroll
        for (int j = 0; j < 8; j++) {
            float v = acc[i][j];
            if (EPI == 1) v += Crow[j];
            if (EPI == 2) v = 0.5f * v * (1.f + erff(v * 0.70710678118654752f));
            Crow[j] = v;
        }
    }
}

// ---------------- embedding: x[t] = tok_emb[idx[t]] + pos_emb[t % T] ----------------
__global__ void embed_kernel(const int* __restrict__ idx,
                             const float* __restrict__ tok,
                             const float* __restrict__ pos,
                             float* __restrict__ x)
{
    int t = blockIdx.x;
    int token = idx[t];
    const float* tr = tok + (size_t)token * DMODEL;
    const float* pr = pos + (size_t)(t & (TSEQ - 1)) * DMODEL;
    float* xr = x + (size_t)t * DMODEL;
    for (int d = threadIdx.x; d < DMODEL; d += blockDim.x)
        xr[d] = tr[d] + pr[d];
}

// ---------------- layernorm (row = 1024, 256 threads) ----------------
__global__ __launch_bounds__(256) void layernorm_kernel(
    const float* __restrict__ x, float* __restrict__ y,
    const float* __restrict__ w, const float* __restrict__ bvec)
{
    __shared__ float sh1[32], sh2[32];
    int row = blockIdx.x;
    const float* px = x + (size_t)row * DMODEL;
    float* py = y + (size_t)row * DMODEL;
    int tid = threadIdx.x;
    int lane = tid & 31, wid = tid >> 5;

    float v[4];
    float s = 0.f, ss = 0.f;
#pragma unroll
    for (int c = 0; c < 4; c++) {
        v[c] = px[tid + c * 256];
        s += v[c];
        ss = fmaf(v[c], v[c], ss);
    }
#pragma unroll
    for (int o = 16; o; o >>= 1) {
        s  += __shfl_xor_sync(0xffffffffu, s,  o);
        ss += __shfl_xor_sync(0xffffffffu, ss, o);
    }
    if (lane == 0) { sh1[wid] = s; sh2[wid] = ss; }
    __syncthreads();
    if (tid < 32) {
        s  = (tid < 8) ? sh1[tid] : 0.f;
        ss = (tid < 8) ? sh2[tid] : 0.f;
#pragma unroll
        for (int o = 4; o; o >>= 1) {
            s  += __shfl_xor_sync(0xffffffffu, s,  o);
            ss += __shfl_xor_sync(0xffffffffu, ss, o);
        }
        if (tid == 0) { sh1[0] = s; sh2[0] = ss; }
    }
    __syncthreads();
    s = sh1[0]; ss = sh2[0];
    float mean = s * (1.f / DMODEL);
    float var  = ss * (1.f / DMODEL) - mean * mean;
    float inv  = rsqrtf(var + 1e-5f);
#pragma unroll
    for (int c = 0; c < 4; c++) {
        int j = tid + c * 256;
        py[j] = (v[c] - mean) * inv * w[j] + bvec[j];
    }
}

// ---------------- attention scores: S[b,h,i,j] = q.k * 0.125, causal only ----------------
__global__ __launch_bounds__(256) void attn_scores_kernel(
    const float* __restrict__ qkv, float* __restrict__ scores)
{
    int it = blockIdx.y, jt = blockIdx.x;
    if (jt > it) return;                       // fully masked tile
    int bh = blockIdx.z;
    int b = bh >> 4, h = bh & 15;
    const float* qb = qkv + (size_t)b * TSEQ * 3 * DMODEL + h * HDIM;
    const float* kb = qb + DMODEL;

    __shared__ float Qs[64][65];
    __shared__ float Ks[64][65];
    int tid = threadIdx.x;
    int row = tid >> 2;
    int c0  = (tid & 3) * 16;
    const float* qrow = qb + (size_t)(it * 64 + row) * 3 * DMODEL + c0;
    const float* krow = kb + (size_t)(jt * 64 + row) * 3 * DMODEL + c0;
#pragma unroll
    for (int c = 0; c < 16; c += 4) {
        float4 q4 = *(const float4*)(qrow + c);
        float4 k4 = *(const float4*)(krow + c);
        Qs[row][c0+c+0] = q4.x; Qs[row][c0+c+1] = q4.y;
        Qs[row][c0+c+2] = q4.z; Qs[row][c0+c+3] = q4.w;
        Ks[row][c0+c+0] = k4.x; Ks[row][c0+c+1] = k4.y;
        Ks[row][c0+c+2] = k4.z; Ks[row][c0+c+3] = k4.w;
    }
    __syncthreads();

    int tx = tid & 15, ty = tid >> 4;
    float acc[4][4] = {};
#pragma unroll
    for (int kk = 0; kk < 64; kk++) {
        float ra[4], rb[4];
#pragma unroll
        for (int i = 0; i < 4; i++) ra[i] = Qs[ty*4 + i][kk];
#pragma unroll
        for (int j = 0; j < 4; j++) rb[j] = Ks[tx*4 + j][kk];
#pragma unroll
        for (int i = 0; i < 4; i++)
#pragma unroll
            for (int j = 0; j < 4; j++)
                acc[i][j] = fmaf(ra[i], rb[j], acc[i][j]);
    }
#pragma unroll
    for (int ii = 0; ii < 4; ii++) {
        int i = it * 64 + ty * 4 + ii;
#pragma unroll
        for (int jj = 0; jj < 4; jj++) {
            int j = jt * 64 + tx * 4 + jj;
            if (j <= i)
                scores[((size_t)bh * TSEQ + i) * TSEQ + j] = acc[ii][jj] * 0.125f;
        }
    }
}

// ---------------- causal softmax in place (zero-fills j > i) ----------------
__global__ __launch_bounds__(256) void softmax_causal_kernel(float* __restrict__ attn)
{
    __shared__ float sh[32];
    int row = blockIdx.x;               // 0..B*H*T-1
    int i = row & (TSEQ - 1);
    float* p = attn + (size_t)row * TSEQ;
    int tid = threadIdx.x;
    int lane = tid & 31, wid = tid >> 5;

    float m = -INFINITY;
    for (int j = tid; j <= i; j += 256) m = fmaxf(m, p[j]);
#pragma unroll
    for (int o = 16; o; o >>= 1) m = fmaxf(m, __shfl_xor_sync(0xffffffffu, m, o));
    if (lane == 0) sh[wid] = m;
    __syncthreads();
    if (tid < 32) {
        m = (tid < 8) ? sh[tid] : -INFINITY;
#pragma unroll
        for (int o = 4; o; o >>= 1) m = fmaxf(m, __shfl_xor_sync(0xffffffffu, m, o));
        if (tid == 0) sh[0] = m;
    }
    __syncthreads();
    m = sh[0];
    __syncthreads();

    float s = 0.f;
    for (int j = tid; j <= i; j += 256) s += expf(p[j] - m);
#pragma unroll
    for (int o = 16; o; o >>= 1) s += __shfl_xor_sync(0xffffffffu, s, o);
    if (lane == 0) sh[wid] = s;
    __syncthreads();
    if (tid < 32) {
        s = (tid < 8) ? sh[tid] : 0.f;
#pragma unroll
        for (int o = 4; o; o >>= 1) s += __shfl_xor_sync(0xffffffffu, s, o);
        if (tid == 0) sh[0] = s;
    }
    __syncthreads();
    float inv = 1.f / sh[0];

    for (int j = tid; j < TSEQ; j += 256)
        p[j] = (j <= i) ? expf(p[j] - m) * inv : 0.f;
}

// ---------------- O = attn @ V  (per b,h; 64-row tile, full 64 cols) ----------------
__global__ __launch_bounds__(256) void attn_o_kernel(
    const float* __restrict__ attn, const float* __restrict__ qkv, float* __restrict__ o)
{
    int bh = blockIdx.z;
    int b = bh >> 4, h = bh & 15;
    int it = blockIdx.y;
    const float* Ab = attn + (size_t)bh * TSEQ * TSEQ;
    const float* Vb = qkv + (size_t)b * TSEQ * 3 * DMODEL + 2 * DMODEL + h * HDIM;
    float* Ob = o + (size_t)b * TSEQ * DMODEL + h * HDIM;

    __shared__ float As_[16][64];
    __shared__ float Bs[16][64];
    int tid = threadIdx.x;
    int tx = tid & 15, ty = tid >> 4;
    int arow = tid >> 2, ak = (tid & 3) * 4;   // A tile [64 x 16]
    int vk = tid >> 4, vd = (tid & 15) * 4;    // V tile [16 x 64]

    float acc[4][4] = {};
    int Kend = (it + 1) * 64;                  // causal: attn is 0 beyond row block
    for (int k0 = 0; k0 < Kend; k0 += 16) {
        float4 a4 = *(const float4*)(Ab + (size_t)(it * 64 + arow) * TSEQ + k0 + ak);
        As_[ak+0][arow] = a4.x; As_[ak+1][arow] = a4.y;
        As_[ak+2][arow] = a4.z; As_[ak+3][arow] = a4.w;
        *(float4*)&Bs[vk][vd] = *(const float4*)(Vb + (size_t)(k0 + vk) * 3 * DMODEL + vd);
        __syncthreads();
#pragma unroll
        for (int kk = 0; kk < 16; kk++) {
            float ra[4], rb[4];
            *(float4*)ra = *(const float4*)&As_[kk][ty*4];
            *(float4*)rb = *(const float4*)&Bs[kk][tx*4];
#pragma unroll
            for (int i = 0; i < 4; i++)
#pragma unroll
                for (int j = 0; j < 4; j++)
                    acc[i][j] = fmaf(ra[i], rb[j], acc[i][j]);
        }
        __syncthreads();
    }
#pragma unroll
    for (int ii = 0; ii < 4; ii++) {
        int i = it * 64 + ty * 4 + ii;
#pragma unroll
        for (int jj = 0; jj < 4; jj++)
            Ob[(size_t)i * DMODEL + tx * 4 + jj] = acc[ii][jj];
    }
}

// ---------------- launch ----------------
extern "C" void kernel_launch(void* const* d_in, const int* in_sizes, int n_in,
                              void* d_out, int out_size)
{
    (void)in_sizes; (void)n_in; (void)out_size;
    const int*   idx     = (const int*)  d_in[0];
    const float* tok_emb = (const float*)d_in[1];
    const float* pos_emb = (const float*)d_in[2];
    const float* ln1_w   = (const float*)d_in[3];
    const float* ln1_b   = (const float*)d_in[4];
    const float* qkv_w   = (const float*)d_in[5];
    const float* out_w   = (const float*)d_in[6];
    const float* ln2_w   = (const float*)d_in[7];
    const float* ln2_b   = (const float*)d_in[8];
    const float* ffn1_w  = (const float*)d_in[9];
    const float* ffn2_w  = (const float*)d_in[10];
    const float* lnf_w   = (const float*)d_in[11];
    const float* lnf_b   = (const float*)d_in[12];
    float* out = (float*)d_out;

    float *x, *h, *qkv, *attn, *o, *ffn;
    cudaGetSymbolAddress((void**)&x,    g_x);
    cudaGetSymbolAddress((void**)&h,    g_h);
    cudaGetSymbolAddress((void**)&qkv,  g_qkv);
    cudaGetSymbolAddress((void**)&attn, g_attn);
    cudaGetSymbolAddress((void**)&o,    g_o);
    cudaGetSymbolAddress((void**)&ffn,  g_ffn);

    embed_kernel<<<MTOK, 256>>>(idx, tok_emb, pos_emb, x);

    for (int l = 0; l < NL; l++) {
        // --- attention block ---
        layernorm_kernel<<<MTOK, 256>>>(x, h, ln1_w + l * DMODEL, ln1_b + l * DMODEL);
        gemm_nt<0><<<dim3(3 * DMODEL / 128, MTOK / 128), 256>>>(
            h, qkv_w + (size_t)l * 3 * DMODEL * DMODEL, qkv,
            MTOK, 3 * DMODEL, DMODEL, DMODEL, DMODEL, 3 * DMODEL);
        attn_scores_kernel<<<dim3(TSEQ / 64, TSEQ / 64, BATCH * NH), 256>>>(qkv, attn);
        softmax_causal_kernel<<<BATCH * NH * TSEQ, 256>>>(attn);
        attn_o_kernel<<<dim3(1, TSEQ / 64, BATCH * NH), 256>>>(attn, qkv, o);
        gemm_nt<1><<<dim3(DMODEL / 128, MTOK / 128), 256>>>(
            o, out_w + (size_t)l * DMODEL * DMODEL, x,
            MTOK, DMODEL, DMODEL, DMODEL, DMODEL, DMODEL);
        // --- FFN block ---
        layernorm_kernel<<<MTOK, 256>>>(x, h, ln2_w + l * DMODEL, ln2_b + l * DMODEL);
        gemm_nt<2><<<dim3(DFF / 128, MTOK / 128), 256>>>(
            h, ffn1_w + (size_t)l * DFF * DMODEL, ffn,
            MTOK, DFF, DMODEL, DMODEL, DMODEL, DFF);
        gemm_nt<1><<<dim3(DMODEL / 128, MTOK / 128), 256>>>(
            ffn, ffn2_w + (size_t)l * DMODEL * DFF, x,
            MTOK, DMODEL, DFF, DFF, DFF, DMODEL);
    }

    layernorm_kernel<<<MTOK, 256>>>(x, h, lnf_w, lnf_b);
    gemm_nt<0><<<dim3(VOC / 128, MTOK / 128), 256>>>(
        h, tok_emb, out, MTOK, VOC, DMODEL, DMODEL, DMODEL, VOC);
}

// round 2
// speedup vs baseline: 2.3464x; 2.3464x over previous
#include <cuda_runtime.h>
#include <cuda_bf16.h>
#include <math.h>
#include <stdint.h>

// ---------------- problem constants ----------------
#define NL     6
#define DMODEL 1024
#define DFF    4096
#define VOC    32000
#define NH     16
#define HDIM   64
#define BATCH  2
#define TSEQ   1024
#define MTOK   (BATCH*TSEQ)   // 2048

typedef __nv_bfloat16 bf16;

// ---------------- scratch (static device globals; no allocation) ----------------
__device__ float g_x   [MTOK * DMODEL];
__device__ float g_qkv [MTOK * 3 * DMODEL];
__device__ float g_attn[(size_t)BATCH * NH * TSEQ * TSEQ];

__device__ __align__(16) bf16 g_hh[MTOK * DMODEL], g_hl[MTOK * DMODEL];
__device__ __align__(16) bf16 g_oh[MTOK * DMODEL], g_ol[MTOK * DMODEL];
__device__ __align__(16) bf16 g_fh[(size_t)MTOK * DFF], g_fl[(size_t)MTOK * DFF];

__device__ __align__(16) bf16 g_wqh[(size_t)NL*3*DMODEL*DMODEL], g_wql[(size_t)NL*3*DMODEL*DMODEL];
__device__ __align__(16) bf16 g_woh[(size_t)NL*DMODEL*DMODEL],   g_wol[(size_t)NL*DMODEL*DMODEL];
__device__ __align__(16) bf16 g_w1h[(size_t)NL*DFF*DMODEL],      g_w1l[(size_t)NL*DFF*DMODEL];
__device__ __align__(16) bf16 g_w2h[(size_t)NL*DMODEL*DFF],      g_w2l[(size_t)NL*DMODEL*DFF];
__device__ __align__(16) bf16 g_eh [(size_t)VOC*DMODEL],         g_el [(size_t)VOC*DMODEL];

// ---------------- helpers ----------------
__device__ __forceinline__ void f2hilo(float x, bf16& h, bf16& l) {
    h = __float2bfloat16(x);
    l = __float2bfloat16(x - __bfloat162float(h));
}

__device__ __forceinline__ void cp_async16(uint32_t s, const void* g) {
    asm volatile("cp.async.cg.shared.global [%0], [%1], 16;\n" :: "r"(s), "l"(g));
}
__device__ __forceinline__ void cp_commit() { asm volatile("cp.async.commit_group;\n"); }
template<int N> __device__ __forceinline__ void cp_wait() {
    asm volatile("cp.async.wait_group %0;\n" :: "n"(N));
}

__device__ __forceinline__ void ldsm4(uint32_t* r, uint32_t addr) {
    asm volatile("ldmatrix.sync.aligned.m8n8.x4.shared.b16 {%0,%1,%2,%3}, [%4];\n"
        : "=r"(r[0]), "=r"(r[1]), "=r"(r[2]), "=r"(r[3]) : "r"(addr));
}

__device__ __forceinline__ void mma16816(float* c, const uint32_t* a, uint32_t b0, uint32_t b1) {
    asm volatile(
        "mma.sync.aligned.m16n8k16.row.col.f32.bf16.bf16.f32 "
        "{%0,%1,%2,%3}, {%4,%5,%6,%7}, {%8,%9}, {%0,%1,%2,%3};\n"
        : "+f"(c[0]), "+f"(c[1]), "+f"(c[2]), "+f"(c[3])
        : "r"(a[0]), "r"(a[1]), "r"(a[2]), "r"(a[3]), "r"(b0), "r"(b1));
}

// ---------------- fp32 -> (hi,lo) bf16 conversion ----------------
__global__ __launch_bounds__(256) void cvt_hilo(const float* __restrict__ x,
                                                bf16* __restrict__ h, bf16* __restrict__ l,
                                                int n)
{
    int i = (blockIdx.x * 256 + threadIdx.x) * 4;
    if (i >= n) return;
    float4 v = *(const float4*)(x + i);
    bf16 h0, h1, h2, h3, l0, l1, l2, l3;
    f2hilo(v.x, h0, l0); f2hilo(v.y, h1, l1);
    f2hilo(v.z, h2, l2); f2hilo(v.w, h3, l3);
    h[i+0] = h0; h[i+1] = h1; h[i+2] = h2; h[i+3] = h3;
    l[i+0] = l0; l[i+1] = l1; l[i+2] = l2; l[i+3] = l3;
}

// ---------------- bf16x2 split-precision GEMM ----------------
// C[M,N] = (Ah+Al)[M,K] * (Bh+Bl)[N,K]^T  (dropping Al*Bl)
// 128x128 block, BK=32, 256 threads (8 warps, 2x4), warp tile 64x32.
// EPI: 0 = store fp32, 1 = C += acc (residual), 2 = gelu -> (Ch,Cl) bf16
#define EPI_STORE 0
#define EPI_ADD   1
#define EPI_GELU  2

template<int EPI>
__global__ __launch_bounds__(256) void gemm_bf16x2(
    const bf16* __restrict__ Ah, const bf16* __restrict__ Al,
    const bf16* __restrict__ Bh, const bf16* __restrict__ Bl,
    float* __restrict__ C, bf16* __restrict__ Ch, bf16* __restrict__ Cl,
    int M, int N, int K)
{
    extern __shared__ uint8_t smem[];
    const uint32_t smem_u32 = (uint32_t)__cvta_generic_to_shared(smem);
    // layout: stage(2) x tensor(4: Ah,Al,Bh,Bl) x 8192B   (tile 128 rows x 64B)

    const int tid  = threadIdx.x;
    const int lane = tid & 31;
    const int wid  = tid >> 5;
    const int wm   = wid & 1;       // 0..1
    const int wn   = wid >> 1;      // 0..3
    const int bm   = blockIdx.y * 128;
    const int bn   = blockIdx.x * 128;

    // loader mapping: thread -> (chunk, 2 rows)
    const int lch = tid & 3;        // 16B chunk 0..3
    const int lr0 = tid >> 2;       // row 0..63 (and +64)

    const bf16* srcs[4] = { Ah + (size_t)bm * K, Al + (size_t)bm * K,
                            Bh + (size_t)bn * K, Bl + (size_t)bn * K };

    float acc[4][4][4];
#pragma unroll
    for (int a = 0; a < 4; a++)
#pragma unroll
        for (int b = 0; b < 4; b++)
#pragma unroll
            for (int c = 0; c < 4; c++) acc[a][b][c] = 0.f;

    const int ntiles = K >> 5;

    // --- stage load ---
    auto load_stage = [&](int st, int k0) {
#pragma unroll
        for (int tz = 0; tz < 4; tz++) {
            const bf16* src = srcs[tz];
            uint32_t sb = smem_u32 + st * 32768 + tz * 8192;
#pragma unroll
            for (int rr = 0; rr < 2; rr++) {
                int r = lr0 + rr * 64;
                const void* gp = src + (size_t)r * K + k0 + lch * 8;
                uint32_t sp = sb + r * 64 + ((lch ^ (r & 3)) << 4);
                cp_async16(sp, gp);
            }
        }
    };

    load_stage(0, 0);
    cp_commit();

    for (int t = 0; t < ntiles; t++) {
        if (t + 1 < ntiles) {
            load_stage((t + 1) & 1, (t + 1) << 5);
            cp_commit();
            cp_wait<1>();
        } else {
            cp_wait<0>();
        }
        __syncthreads();

        const int st = t & 1;
        const uint32_t bAh = smem_u32 + st * 32768;
        const uint32_t bAl = bAh + 8192;
        const uint32_t bBh = bAh + 16384;
        const uint32_t bBl = bAh + 24576;

#pragma unroll
        for (int s = 0; s < 2; s++) {
            uint32_t ah[4][4], al[4][4];
#pragma unroll
            for (int mt = 0; mt < 4; mt++) {
                int row = wm * 64 + mt * 16 + (lane & 15);
                int ch  = 2 * s + (lane >> 4);
                uint32_t off = row * 64 + ((ch ^ (row & 3)) << 4);
                ldsm4(ah[mt], bAh + off);
                ldsm4(al[mt], bAl + off);
            }
            uint32_t bh[2][4], bl[2][4];
#pragma unroll
            for (int p = 0; p < 2; p++) {
                int row = wn * 32 + p * 16 + (lane & 15);
                int ch  = 2 * s + (lane >> 4);
                uint32_t off = row * 64 + ((ch ^ (row & 3)) << 4);
                ldsm4(bh[p], bBh + off);
                ldsm4(bl[p], bBl + off);
            }
#pragma unroll
            for (int mt = 0; mt < 4; mt++) {
#pragma unroll
                for (int nt = 0; nt < 4; nt++) {
                    int p = nt >> 1, q = nt & 1;
                    mma16816(acc[mt][nt], ah[mt], bh[p][q], bh[p][q + 2]);
                    mma16816(acc[mt][nt], ah[mt], bl[p][q], bl[p][q + 2]);
                    mma16816(acc[mt][nt], al[mt], bh[p][q], bh[p][q + 2]);
                }
            }
        }
        __syncthreads();
    }

    // --- epilogue ---
#pragma unroll
    for (int mt = 0; mt < 4; mt++) {
#pragma unroll
        for (int nt = 0; nt < 4; nt++) {
            int row = bm + wm * 64 + mt * 16 + (lane >> 2);
            int col = bn + wn * 32 + nt * 8 + (lane & 3) * 2;
            size_t i0 = (size_t)row * N + col;
            size_t i1 = i0 + (size_t)8 * N;
            float* c = acc[mt][nt];
            if (EPI == EPI_STORE) {
                *(float2*)(C + i0) = make_float2(c[0], c[1]);
                *(float2*)(C + i1) = make_float2(c[2], c[3]);
            } else if (EPI == EPI_ADD) {
                C[i0]   += c[0]; C[i0+1] += c[1];
                C[i1]   += c[2]; C[i1+1] += c[3];
            } else {
#pragma unroll
                for (int e = 0; e < 4; e++) {
                    float v = c[e];
                    float g = 0.5f * v * (1.f + erff(v * 0.70710678118654752f));
                    size_t ii = (e < 2) ? (i0 + e) : (i1 + e - 2);
                    bf16 hh, ll;
                    f2hilo(g, hh, ll);
                    Ch[ii] = hh; Cl[ii] = ll;
                }
            }
        }
    }
}

// ---------------- embedding ----------------
__global__ void embed_kernel(const int* __restrict__ idx,
                             const float* __restrict__ tok,
                             const float* __restrict__ pos,
                             float* __restrict__ x)
{
    int t = blockIdx.x;
    int token = idx[t];
    const float* tr = tok + (size_t)token * DMODEL;
    const float* pr = pos + (size_t)(t & (TSEQ - 1)) * DMODEL;
    float* xr = x + (size_t)t * DMODEL;
    for (int d = threadIdx.x; d < DMODEL; d += blockDim.x)
        xr[d] = tr[d] + pr[d];
}

// ---------------- layernorm: fp32 in, (hi,lo) bf16 out ----------------
__global__ __launch_bounds__(256) void layernorm_kernel(
    const float* __restrict__ x, bf16* __restrict__ yh, bf16* __restrict__ yl,
    const float* __restrict__ w, const float* __restrict__ bvec)
{
    __shared__ float sh1[32], sh2[32];
    int row = blockIdx.x;
    const float* px = x + (size_t)row * DMODEL;
    int tid = threadIdx.x;
    int lane = tid & 31, wid = tid >> 5;

    float v[4];
    float s = 0.f, ss = 0.f;
#pragma unroll
    for (int c = 0; c < 4; c++) {
        v[c] = px[tid + c * 256];
        s += v[c];
        ss = fmaf(v[c], v[c], ss);
    }
#pragma unroll
    for (int o = 16; o; o >>= 1) {
        s  += __shfl_xor_sync(0xffffffffu, s,  o);
        ss += __shfl_xor_sync(0xffffffffu, ss, o);
    }
    if (lane == 0) { sh1[wid] = s; sh2[wid] = ss; }
    __syncthreads();
    if (tid < 32) {
        s  = (tid < 8) ? sh1[tid] : 0.f;
        ss = (tid < 8) ? sh2[tid] : 0.f;
#pragma unroll
        for (int o = 4; o; o >>= 1) {
            s  += __shfl_xor_sync(0xffffffffu, s,  o);
            ss += __shfl_xor_sync(0xffffffffu, ss, o);
        }
        if (tid == 0) { sh1[0] = s; sh2[0] = ss; }
    }
    __syncthreads();
    s = sh1[0]; ss = sh2[0];
    float mean = s * (1.f / DMODEL);
    float var  = ss * (1.f / DMODEL) - mean * mean;
    float inv  = rsqrtf(var + 1e-5f);
#pragma unroll
    for (int c = 0; c < 4; c++) {
        int j = tid + c * 256;
        float y = (v[c] - mean) * inv * w[j] + bvec[j];
        bf16 hh, ll;
        f2hilo(y, hh, ll);
        yh[(size_t)row * DMODEL + j] = hh;
        yl[(size_t)row * DMODEL + j] = ll;
    }
}

// ---------------- attention scores (fp32) ----------------
__global__ __launch_bounds__(256) void attn_scores_kernel(
    const float* __restrict__ qkv, float* __restrict__ scores)
{
    int it = blockIdx.y, jt = blockIdx.x;
    if (jt > it) return;
    int bh = blockIdx.z;
    int b = bh >> 4, h = bh & 15;
    const float* qb = qkv + (size_t)b * TSEQ * 3 * DMODEL + h * HDIM;
    const float* kb = qb + DMODEL;

    __shared__ float Qs[64][65];
    __shared__ float Ks[64][65];
    int tid = threadIdx.x;
    int row = tid >> 2;
    int c0  = (tid & 3) * 16;
    const float* qrow = qb + (size_t)(it * 64 + row) * 3 * DMODEL + c0;
    const float* krow = kb + (size_t)(jt * 64 + row) * 3 * DMODEL + c0;
#pragma unroll
    for (int c = 0; c < 16; c += 4) {
        float4 q4 = *(const float4*)(qrow + c);
        float4 k4 = *(const float4*)(krow + c);
        Qs[row][c0+c+0] = q4.x; Qs[row][c0+c+1] = q4.y;
        Qs[row][c0+c+2] = q4.z; Qs[row][c0+c+3] = q4.w;
        Ks[row][c0+c+0] = k4.x; Ks[row][c0+c+1] = k4.y;
        Ks[row][c0+c+2] = k4.z; Ks[row][c0+c+3] = k4.w;
    }
    __syncthreads();

    int tx = tid & 15, ty = tid >> 4;
    float acc[4][4] = {};
#pragma unroll
    for (int kk = 0; kk < 64; kk++) {
        float ra[4], rb[4];
#pragma unroll
        for (int i = 0; i < 4; i++) ra[i] = Qs[ty*4 + i][kk];
#pragma unroll
        for (int j = 0; j < 4; j++) rb[j] = Ks[tx*4 + j][kk];
#pragma unroll
        for (int i = 0; i < 4; i++)
#pragma unroll
            for (int j = 0; j < 4; j++)
                acc[i][j] = fmaf(ra[i], rb[j], acc[i][j]);
    }
#pragma unroll
    for (int ii = 0; ii < 4; ii++) {
        int i = it * 64 + ty * 4 + ii;
#pragma unroll
        for (int jj = 0; jj < 4; jj++) {
            int j = jt * 64 + tx * 4 + jj;
            if (j <= i)
                scores[((size_t)bh * TSEQ + i) * TSEQ + j] = acc[ii][jj] * 0.125f;
        }
    }
}

// ---------------- causal softmax in place ----------------
__global__ __launch_bounds__(256) void softmax_causal_kernel(float* __restrict__ attn)
{
    __shared__ float sh[32];
    int row = blockIdx.x;
    int i = row & (TSEQ - 1);
    float* p = attn + (size_t)row * TSEQ;
    int tid = threadIdx.x;
    int lane = tid & 31, wid = tid >> 5;

    float m = -INFINITY;
    for (int j = tid; j <= i; j += 256) m = fmaxf(m, p[j]);
#pragma unroll
    for (int o = 16; o; o >>= 1) m = fmaxf(m, __shfl_xor_sync(0xffffffffu, m, o));
    if (lane == 0) sh[wid] = m;
    __syncthreads();
    if (tid < 32) {
        m = (tid < 8) ? sh[tid] : -INFINITY;
#pragma unroll
        for (int o = 4; o; o >>= 1) m = fmaxf(m, __shfl_xor_sync(0xffffffffu, m, o));
        if (tid == 0) sh[0] = m;
    }
    __syncthreads();
    m = sh[0];
    __syncthreads();

    float s = 0.f;
    for (int j = tid; j <= i; j += 256) s += expf(p[j] - m);
#pragma unroll
    for (int o = 16; o; o >>= 1) s += __shfl_xor_sync(0xffffffffu, s, o);
    if (lane == 0) sh[wid] = s;
    __syncthreads();
    if (tid < 32) {
        s = (tid < 8) ? sh[tid] : 0.f;
#pragma unroll
        for (int o = 4; o; o >>= 1) s += __shfl_xor_sync(0xffffffffu, s, o);
        if (tid == 0) sh[0] = s;
    }
    __syncthreads();
    float inv = 1.f / sh[0];

    for (int j = tid; j < TSEQ; j += 256)
        p[j] = (j <= i) ? expf(p[j] - m) * inv : 0.f;
}

// ---------------- O = attn @ V -> (hi,lo) bf16 ----------------
__global__ __launch_bounds__(256) void attn_o_kernel(
    const float* __restrict__ attn, const float* __restrict__ qkv,
    bf16* __restrict__ oh, bf16* __restrict__ ol)
{
    int bh = blockIdx.z;
    int b = bh >> 4, h = bh & 15;
    int it = blockIdx.y;
    const float* Ab = attn + (size_t)bh * TSEQ * TSEQ;
    const float* Vb = qkv + (size_t)b * TSEQ * 3 * DMODEL + 2 * DMODEL + h * HDIM;
    size_t obase = (size_t)b * TSEQ * DMODEL + h * HDIM;

    __shared__ float As_[16][64];
    __shared__ float Bs[16][64];
    int tid = threadIdx.x;
    int tx = tid & 15, ty = tid >> 4;
    int arow = tid >> 2, ak = (tid & 3) * 4;
    int vk = tid >> 4, vd = (tid & 15) * 4;

    float acc[4][4] = {};
    int Kend = (it + 1) * 64;
    for (int k0 = 0; k0 < Kend; k0 += 16) {
        float4 a4 = *(const float4*)(Ab + (size_t)(it * 64 + arow) * TSEQ + k0 + ak);
        As_[ak+0][arow] = a4.x; As_[ak+1][arow] = a4.y;
        As_[ak+2][arow] = a4.z; As_[ak+3][arow] = a4.w;
        *(float4*)&Bs[vk][vd] = *(const float4*)(Vb + (size_t)(k0 + vk) * 3 * DMODEL + vd);
        __syncthreads();
#pragma unroll
        for (int kk = 0; kk < 16; kk++) {
            float ra[4], rb[4];
            *(float4*)ra = *(const float4*)&As_[kk][ty*4];
            *(float4*)rb = *(const float4*)&Bs[kk][tx*4];
#pragma unroll
            for (int i = 0; i < 4; i++)
#pragma unroll
                for (int j = 0; j < 4; j++)
                    acc[i][j] = fmaf(ra[i], rb[j], acc[i][j]);
        }
        __syncthreads();
    }
#pragma unroll
    for (int ii = 0; ii < 4; ii++) {
        int i = it * 64 + ty * 4 + ii;
#pragma unroll
        for (int jj = 0; jj < 4; jj++) {
            bf16 hh, ll;
            f2hilo(acc[ii][jj], hh, ll);
            size_t o = obase + (size_t)i * DMODEL + tx * 4 + jj;
            oh[o] = hh; ol[o] = ll;
        }
    }
}

// ---------------- launch ----------------
extern "C" void kernel_launch(void* const* d_in, const int* in_sizes, int n_in,
                              void* d_out, int out_size)
{
    (void)in_sizes; (void)n_in; (void)out_size;
    const int*   idx     = (const int*)  d_in[0];
    const float* tok_emb = (const float*)d_in[1];
    const float* pos_emb = (const float*)d_in[2];
    const float* ln1_w   = (const float*)d_in[3];
    const float* ln1_b   = (const float*)d_in[4];
    const float* qkv_w   = (const float*)d_in[5];
    const float* out_w   = (const float*)d_in[6];
    const float* ln2_w   = (const float*)d_in[7];
    const float* ln2_b   = (const float*)d_in[8];
    const float* ffn1_w  = (const float*)d_in[9];
    const float* ffn2_w  = (const float*)d_in[10];
    const float* lnf_w   = (const float*)d_in[11];
    const float* lnf_b   = (const float*)d_in[12];
    float* out = (float*)d_out;

    float *x, *qkv, *attn;
    bf16 *hh, *hl, *oh, *ol, *fh, *fl;
    bf16 *wqh, *wql, *woh, *wol, *w1h, *w1l, *w2h, *w2l, *eh, *el;
    cudaGetSymbolAddress((void**)&x,    g_x);
    cudaGetSymbolAddress((void**)&qkv,  g_qkv);
    cudaGetSymbolAddress((void**)&attn, g_attn);
    cudaGetSymbolAddress((void**)&hh,   g_hh);  cudaGetSymbolAddress((void**)&hl, g_hl);
    cudaGetSymbolAddress((void**)&oh,   g_oh);  cudaGetSymbolAddress((void**)&ol, g_ol);
    cudaGetSymbolAddress((void**)&fh,   g_fh);  cudaGetSymbolAddress((void**)&fl, g_fl);
    cudaGetSymbolAddress((void**)&wqh,  g_wqh); cudaGetSymbolAddress((void**)&wql, g_wql);
    cudaGetSymbolAddress((void**)&woh,  g_woh); cudaGetSymbolAddress((void**)&wol, g_wol);
    cudaGetSymbolAddress((void**)&w1h,  g_w1h); cudaGetSymbolAddress((void**)&w1l, g_w1l);
    cudaGetSymbolAddress((void**)&w2h,  g_w2h); cudaGetSymbolAddress((void**)&w2l, g_w2l);
    cudaGetSymbolAddress((void**)&eh,   g_eh);  cudaGetSymbolAddress((void**)&el,  g_el);

    cudaFuncSetAttribute(gemm_bf16x2<EPI_STORE>, cudaFuncAttributeMaxDynamicSharedMemorySize, 65536);
    cudaFuncSetAttribute(gemm_bf16x2<EPI_ADD>,   cudaFuncAttributeMaxDynamicSharedMemorySize, 65536);
    cudaFuncSetAttribute(gemm_bf16x2<EPI_GELU>,  cudaFuncAttributeMaxDynamicSharedMemorySize, 65536);

    // weight / embedding split to (hi, lo) bf16
    {
        int n;
        n = NL*3*DMODEL*DMODEL; cvt_hilo<<<n/1024, 256>>>(qkv_w,  wqh, wql, n);
        n = NL*DMODEL*DMODEL;   cvt_hilo<<<n/1024, 256>>>(out_w,  woh, wol, n);
        n = NL*DFF*DMODEL;      cvt_hilo<<<n/1024, 256>>>(ffn1_w, w1h, w1l, n);
        n = NL*DMODEL*DFF;      cvt_hilo<<<n/1024, 256>>>(ffn2_w, w2h, w2l, n);
        n = VOC*DMODEL;         cvt_hilo<<<n/1024, 256>>>(tok_emb, eh, el, n);
    }

    embed_kernel<<<MTOK, 256>>>(idx, tok_emb, pos_emb, x);

    for (int l = 0; l < NL; l++) {
        // --- attention block ---
        layernorm_kernel<<<MTOK, 256>>>(x, hh, hl, ln1_w + l * DMODEL, ln1_b + l * DMODEL);
        gemm_bf16x2<EPI_STORE><<<dim3(3*DMODEL/128, MTOK/128), 256, 65536>>>(
            hh, hl, wqh + (size_t)l*3*DMODEL*DMODEL, wql + (size_t)l*3*DMODEL*DMODEL,
            qkv, nullptr, nullptr, MTOK, 3*DMODEL, DMODEL);
        attn_scores_kernel<<<dim3(TSEQ/64, TSEQ/64, BATCH*NH), 256>>>(qkv, attn);
        softmax_causal_kernel<<<BATCH*NH*TSEQ, 256>>>(attn);
        attn_o_kernel<<<dim3(1, TSEQ/64, BATCH*NH), 256>>>(attn, qkv, oh, ol);
        gemm_bf16x2<EPI_ADD><<<dim3(DMODEL/128, MTOK/128), 256, 65536>>>(
            oh, ol, woh + (size_t)l*DMODEL*DMODEL, wol + (size_t)l*DMODEL*DMODEL,
            x, nullptr, nullptr, MTOK, DMODEL, DMODEL);
        // --- FFN block ---
        layernorm_kernel<<<MTOK, 256>>>(x, hh, hl, ln2_w + l * DMODEL, ln2_b + l * DMODEL);
        gemm_bf16x2<EPI_GELU><<<dim3(DFF/128, MTOK/128), 256, 65536>>>(
            hh, hl, w1h + (size_t)l*DFF*DMODEL, w1l + (size_t)l*DFF*DMODEL,
            nullptr, fh, fl, MTOK, DFF, DMODEL);
        gemm_bf16x2<EPI_ADD><<<dim3(DMODEL/128, MTOK/128), 256, 65536>>>(
            fh, fl, w2h + (size_t)l*DMODEL*DFF, w2l + (size_t)l*DMODEL*DFF,
            x, nullptr, nullptr, MTOK, DMODEL, DFF);
    }

    layernorm_kernel<<<MTOK, 256>>>(x, hh, hl, lnf_w, lnf_b);
    gemm_bf16x2<EPI_STORE><<<dim3(VOC/128, MTOK/128), 256, 65536>>>(
        hh, hl, eh, el, out, nullptr, nullptr, MTOK, VOC, DMODEL);
}

// round 4
// speedup vs baseline: 2.9247x; 1.2465x over previous
#include <cuda_runtime.h>
#include <cuda_bf16.h>
#include <math.h>
#include <stdint.h>

// ---------------- problem constants ----------------
#define NL     6
#define DMODEL 1024
#define DFF    4096
#define VOC    32000
#define NH     16
#define HDIM   64
#define BATCH  2
#define TSEQ   1024
#define MTOK   (BATCH*TSEQ)   // 2048

typedef __nv_bfloat16 bf16;

// ---------------- scratch (static device globals; no allocation) ----------------
__device__ float g_x[MTOK * DMODEL];

__device__ __align__(16) bf16 g_hh[MTOK * DMODEL], g_hl[MTOK * DMODEL];
__device__ __align__(16) bf16 g_qkvh[(size_t)MTOK * 3 * DMODEL], g_qkvl[(size_t)MTOK * 3 * DMODEL];
__device__ __align__(16) bf16 g_oh[MTOK * DMODEL], g_ol[MTOK * DMODEL];
__device__ __align__(16) bf16 g_fh[(size_t)MTOK * DFF], g_fl[(size_t)MTOK * DFF];

__device__ __align__(16) bf16 g_wqh[(size_t)NL*3*DMODEL*DMODEL], g_wql[(size_t)NL*3*DMODEL*DMODEL];
__device__ __align__(16) bf16 g_woh[(size_t)NL*DMODEL*DMODEL],   g_wol[(size_t)NL*DMODEL*DMODEL];
__device__ __align__(16) bf16 g_w1h[(size_t)NL*DFF*DMODEL],      g_w1l[(size_t)NL*DFF*DMODEL];
__device__ __align__(16) bf16 g_w2h[(size_t)NL*DMODEL*DFF],      g_w2l[(size_t)NL*DMODEL*DFF];
__device__ __align__(16) bf16 g_eh [(size_t)VOC*DMODEL],         g_el [(size_t)VOC*DMODEL];

// ---------------- helpers ----------------
__device__ __forceinline__ void f2hilo(float x, bf16& h, bf16& l) {
    h = __float2bfloat16(x);
    l = __float2bfloat16(x - __bfloat162float(h));
}
__device__ __forceinline__ uint32_t packbf(bf16 a, bf16 b) {
    __nv_bfloat162 t; t.x = a; t.y = b;
    return *(uint32_t*)&t;
}

__device__ __forceinline__ void cp_async16(uint32_t s, const void* g) {
    asm volatile("cp.async.cg.shared.global [%0], [%1], 16;\n" :: "r"(s), "l"(g));
}
__device__ __forceinline__ void cp_commit() { asm volatile("cp.async.commit_group;\n"); }
template<int N> __device__ __forceinline__ void cp_wait() {
    asm volatile("cp.async.wait_group %0;\n" :: "n"(N));
}

__device__ __forceinline__ void ldsm4(uint32_t* r, uint32_t addr) {
    asm volatile("ldmatrix.sync.aligned.m8n8.x4.shared.b16 {%0,%1,%2,%3}, [%4];\n"
        : "=r"(r[0]), "=r"(r[1]), "=r"(r[2]), "=r"(r[3]) : "r"(addr));
}
__device__ __forceinline__ void ldsm4t(uint32_t* r, uint32_t addr) {
    asm volatile("ldmatrix.sync.aligned.m8n8.x4.trans.shared.b16 {%0,%1,%2,%3}, [%4];\n"
        : "=r"(r[0]), "=r"(r[1]), "=r"(r[2]), "=r"(r[3]) : "r"(addr));
}

__device__ __forceinline__ void mma16816(float* c, const uint32_t* a, uint32_t b0, uint32_t b1) {
    asm volatile(
        "mma.sync.aligned.m16n8k16.row.col.f32.bf16.bf16.f32 "
        "{%0,%1,%2,%3}, {%4,%5,%6,%7}, {%8,%9}, {%0,%1,%2,%3};\n"
        : "+f"(c[0]), "+f"(c[1]), "+f"(c[2]), "+f"(c[3])
        : "r"(a[0]), "r"(a[1]), "r"(a[2]), "r"(a[3]), "r"(b0), "r"(b1));
}

// ---------------- fp32 -> (hi,lo) bf16 conversion ----------------
__global__ __launch_bounds__(256) void cvt_hilo(const float* __restrict__ x,
                                                bf16* __restrict__ h, bf16* __restrict__ l,
                                                int n)
{
    int i = (blockIdx.x * 256 + threadIdx.x) * 4;
    if (i >= n) return;
    float4 v = *(const float4*)(x + i);
    bf16 h0, h1, h2, h3, l0, l1, l2, l3;
    f2hilo(v.x, h0, l0); f2hilo(v.y, h1, l1);
    f2hilo(v.z, h2, l2); f2hilo(v.w, h3, l3);
    h[i+0] = h0; h[i+1] = h1; h[i+2] = h2; h[i+3] = h3;
    l[i+0] = l0; l[i+1] = l1; l[i+2] = l2; l[i+3] = l3;
}

// ---------------- bf16x2 split-precision GEMM (mma.sync) ----------------
// C[M,N] = (Ah+Al)[M,K] * (Bh+Bl)[N,K]^T  (dropping Al*Bl)
// 128x128 block, BK=32, 256 threads (8 warps, 2x4), warp tile 64x32.
#define EPI_STORE 0
#define EPI_ADD   1
#define EPI_GELU  2
#define EPI_HILO  3

template<int EPI>
__global__ __launch_bounds__(256) void gemm_bf16x2(
    const bf16* __restrict__ Ah, const bf16* __restrict__ Al,
    const bf16* __restrict__ Bh, const bf16* __restrict__ Bl,
    float* __restrict__ C, bf16* __restrict__ Ch, bf16* __restrict__ Cl,
    int M, int N, int K)
{
    extern __shared__ uint8_t smem[];
    const uint32_t smem_u32 = (uint32_t)__cvta_generic_to_shared(smem);

    const int tid  = threadIdx.x;
    const int lane = tid & 31;
    const int wid  = tid >> 5;
    const int wm   = wid & 1;
    const int wn   = wid >> 1;
    const int bm   = blockIdx.y * 128;
    const int bn   = blockIdx.x * 128;

    const int lch = tid & 3;
    const int lr0 = tid >> 2;

    const bf16* srcs[4] = { Ah + (size_t)bm * K, Al + (size_t)bm * K,
                            Bh + (size_t)bn * K, Bl + (size_t)bn * K };

    float acc[4][4][4];
#pragma unroll
    for (int a = 0; a < 4; a++)
#pragma unroll
        for (int b = 0; b < 4; b++)
#pragma unroll
            for (int c = 0; c < 4; c++) acc[a][b][c] = 0.f;

    const int ntiles = K >> 5;

    auto load_stage = [&](int st, int k0) {
#pragma unroll
        for (int tz = 0; tz < 4; tz++) {
            const bf16* src = srcs[tz];
            uint32_t sb = smem_u32 + st * 32768 + tz * 8192;
#pragma unroll
            for (int rr = 0; rr < 2; rr++) {
                int r = lr0 + rr * 64;
                const void* gp = src + (size_t)r * K + k0 + lch * 8;
                uint32_t sp = sb + r * 64 + ((lch ^ (r & 3)) << 4);
                cp_async16(sp, gp);
            }
        }
    };

    load_stage(0, 0);
    cp_commit();

    for (int t = 0; t < ntiles; t++) {
        if (t + 1 < ntiles) {
            load_stage((t + 1) & 1, (t + 1) << 5);
            cp_commit();
            cp_wait<1>();
        } else {
            cp_wait<0>();
        }
        __syncthreads();

        const int st = t & 1;
        const uint32_t bAh = smem_u32 + st * 32768;
        const uint32_t bAl = bAh + 8192;
        const uint32_t bBh = bAh + 16384;
        const uint32_t bBl = bAh + 24576;

#pragma unroll
        for (int s = 0; s < 2; s++) {
            uint32_t ah[4][4], al[4][4];
#pragma unroll
            for (int mt = 0; mt < 4; mt++) {
                int row = wm * 64 + mt * 16 + (lane & 15);
                int ch  = 2 * s + (lane >> 4);
                uint32_t off = row * 64 + ((ch ^ (row & 3)) << 4);
                ldsm4(ah[mt], bAh + off);
                ldsm4(al[mt], bAl + off);
            }
            uint32_t bh[2][4], bl[2][4];
#pragma unroll
            for (int p = 0; p < 2; p++) {
                int row = wn * 32 + p * 16 + (lane & 15);
                int ch  = 2 * s + (lane >> 4);
                uint32_t off = row * 64 + ((ch ^ (row & 3)) << 4);
                ldsm4(bh[p], bBh + off);
                ldsm4(bl[p], bBl + off);
            }
            // 3 waves of 16 independent MMAs (break RAW chains)
#pragma unroll
            for (int mt = 0; mt < 4; mt++)
#pragma unroll
                for (int nt = 0; nt < 4; nt++) {
                    int p = nt >> 1, q = nt & 1;
                    mma16816(acc[mt][nt], ah[mt], bh[p][q], bh[p][q + 2]);
                }
#pragma unroll
            for (int mt = 0; mt < 4; mt++)
#pragma unroll
                for (int nt = 0; nt < 4; nt++) {
                    int p = nt >> 1, q = nt & 1;
                    mma16816(acc[mt][nt], ah[mt], bl[p][q], bl[p][q + 2]);
                }
#pragma unroll
            for (int mt = 0; mt < 4; mt++)
#pragma unroll
                for (int nt = 0; nt < 4; nt++) {
                    int p = nt >> 1, q = nt & 1;
                    mma16816(acc[mt][nt], al[mt], bh[p][q], bh[p][q + 2]);
                }
        }
        __syncthreads();
    }

    // --- epilogue ---
#pragma unroll
    for (int mt = 0; mt < 4; mt++) {
#pragma unroll
        for (int nt = 0; nt < 4; nt++) {
            int row = bm + wm * 64 + mt * 16 + (lane >> 2);
            int col = bn + wn * 32 + nt * 8 + (lane & 3) * 2;
            size_t i0 = (size_t)row * N + col;
            size_t i1 = i0 + (size_t)8 * N;
            float* c = acc[mt][nt];
            if (EPI == EPI_STORE) {
                *(float2*)(C + i0) = make_float2(c[0], c[1]);
                *(float2*)(C + i1) = make_float2(c[2], c[3]);
            } else if (EPI == EPI_ADD) {
                C[i0]   += c[0]; C[i0+1] += c[1];
                C[i1]   += c[2]; C[i1+1] += c[3];
            } else if (EPI == EPI_GELU) {
#pragma unroll
                for (int e = 0; e < 4; e += 2) {
                    size_t ii = (e == 0) ? i0 : i1;
                    float v0 = c[e], v1 = c[e+1];
                    float q0 = 0.5f * v0 * (1.f + erff(v0 * 0.70710678118654752f));
                    float q1 = 0.5f * v1 * (1.f + erff(v1 * 0.70710678118654752f));
                    bf16 h0, l0, h1, l1;
                    f2hilo(q0, h0, l0); f2hilo(q1, h1, l1);
                    *(uint32_t*)(Ch + ii) = packbf(h0, h1);
                    *(uint32_t*)(Cl + ii) = packbf(l0, l1);
                }
            } else {  // EPI_HILO
#pragma unroll
                for (int e = 0; e < 4; e += 2) {
                    size_t ii = (e == 0) ? i0 : i1;
                    bf16 h0, l0, h1, l1;
                    f2hilo(c[e], h0, l0); f2hilo(c[e+1], h1, l1);
                    *(uint32_t*)(Ch + ii) = packbf(h0, h1);
                    *(uint32_t*)(Cl + ii) = packbf(l0, l1);
                }
            }
        }
    }
}

// ---------------- flash attention (split-bf16 mma.sync) ----------------
// q-tile 128 (8 warps x 16 rows), key blocks of 64, online softmax.
// Q/K/V read from split-bf16 qkv [token][3*DMODEL]; O written split-bf16.
__global__ __launch_bounds__(256) void flash_kernel(
    const bf16* __restrict__ qkvh, const bf16* __restrict__ qkvl,
    bf16* __restrict__ oh, bf16* __restrict__ ol)
{
    extern __shared__ uint8_t fsm[];
    const uint32_t sb  = (uint32_t)__cvta_generic_to_shared(fsm);
    const uint32_t sQh = sb, sQl = sb + 16384;
    const uint32_t sKV = sb + 32768;   // + stage*32768 : [Kh|Kl|Vh|Vl] 8KB each

    const int tid = threadIdx.x, lane = tid & 31, w = tid >> 5;
    const int qi = (int)gridDim.x - 1 - (int)blockIdx.x;   // big tiles first
    const int bh = blockIdx.y;
    const int b = bh >> 4, h = bh & 15;
    const int qbase = qi * 128;
    const int nkb = (qbase + 128) >> 6;

    const size_t tb = (size_t)b * TSEQ;
    const bf16* Qh_ = qkvh + tb * 3 * DMODEL + h * HDIM;
    const bf16* Ql_ = qkvl + tb * 3 * DMODEL + h * HDIM;
    const bf16* Kh_ = Qh_ + DMODEL;
    const bf16* Kl_ = Ql_ + DMODEL;
    const bf16* Vh_ = Qh_ + 2 * DMODEL;
    const bf16* Vl_ = Ql_ + 2 * DMODEL;

    auto load_kv = [&](int buf, int kb) {
        uint32_t base = sKV + (uint32_t)buf * 32768;
#pragma unroll
        for (int i = 0; i < 2; i++) {
            int idx = tid * 2 + i;          // 0..511
            int r = idx >> 3, c = idx & 7;
            size_t go = (size_t)(kb * 64 + r) * 3 * DMODEL + c * 8;
            uint32_t so = r * 128 + (((uint32_t)(c ^ (r & 7))) << 4);
            cp_async16(base + so,         Kh_ + go);
            cp_async16(base + 8192 + so,  Kl_ + go);
            cp_async16(base + 16384 + so, Vh_ + go);
            cp_async16(base + 24576 + so, Vl_ + go);
        }
    };

    // Q tile: 128 rows x 64 cols, hi+lo
#pragma unroll
    for (int i = 0; i < 4; i++) {
        int idx = tid * 4 + i;              // 0..1023
        int r = idx >> 3, c = idx & 7;
        size_t go = (size_t)(qbase + r) * 3 * DMODEL + c * 8;
        uint32_t so = r * 128 + (((uint32_t)(c ^ (r & 7))) << 4);
        cp_async16(sQh + so, Qh_ + go);
        cp_async16(sQl + so, Ql_ + go);
    }
    load_kv(0, 0);
    cp_commit();
    if (nkb > 1) { load_kv(1, 1); cp_commit(); cp_wait<1>(); }
    else cp_wait<0>();
    __syncthreads();

    // Q fragments (held in registers for the whole CTA lifetime)
    uint32_t qfh[4][4], qfl[4][4];
#pragma unroll
    for (int s = 0; s < 4; s++) {
        int r = 16 * w + (lane & 15);
        int c = 2 * s + (lane >> 4);
        uint32_t so = r * 128 + (((uint32_t)(c ^ (r & 7))) << 4);
        ldsm4(qfh[s], sQh + so);
        ldsm4(qfl[s], sQl + so);
    }

    float oacc[8][4];
#pragma unroll
    for (int j = 0; j < 8; j++)
#pragma unroll
        for (int c = 0; c < 4; c++) oacc[j][c] = 0.f;
    float mrow0 = -1e30f, mrow1 = -1e30f, lrow0 = 0.f, lrow1 = 0.f;
    const int r0 = qbase + 16 * w + (lane >> 2);   // global q row (and r0+8)

    for (int kb = 0; kb < nkb; kb++) {
        if (kb * 64 <= qbase + 16 * w + 15) {      // block intersects valid region
            uint32_t base = sKV + (uint32_t)(kb & 1) * 32768;
            float sacc[8][4];
#pragma unroll
            for (int j = 0; j < 8; j++)
#pragma unroll
                for (int c = 0; c < 4; c++) sacc[j][c] = 0.f;

#pragma unroll
            for (int p = 0; p < 4; p++) {
                int rr = 16 * p + (lane & 15);
#pragma unroll
                for (int s = 0; s < 4; s++) {
                    int cc = 2 * s + (lane >> 4);
                    uint32_t so = rr * 128 + (((uint32_t)(cc ^ (rr & 7))) << 4);
                    uint32_t kh4[4], kl4[4];
                    ldsm4(kh4, base + so);
                    ldsm4(kl4, base + 8192 + so);
                    mma16816(sacc[2*p],   qfh[s], kh4[0], kh4[2]);
                    mma16816(sacc[2*p+1], qfh[s], kh4[1], kh4[3]);
                    mma16816(sacc[2*p],   qfh[s], kl4[0], kl4[2]);
                    mma16816(sacc[2*p+1], qfh[s], kl4[1], kl4[3]);
                    mma16816(sacc[2*p],   qfl[s], kh4[0], kh4[2]);
                    mma16816(sacc[2*p+1], qfl[s], kh4[1], kh4[3]);
                }
            }
            // scale + causal mask
            int cbase = kb * 64 + 2 * (lane & 3);
#pragma unroll
            for (int j = 0; j < 8; j++) {
                int c0 = cbase + 8 * j;
                sacc[j][0] = (c0     <= r0    ) ? sacc[j][0] * 0.125f : -1e30f;
                sacc[j][1] = (c0 + 1 <= r0    ) ? sacc[j][1] * 0.125f : -1e30f;
                sacc[j][2] = (c0     <= r0 + 8) ? sacc[j][2] * 0.125f : -1e30f;
                sacc[j][3] = (c0 + 1 <= r0 + 8) ? sacc[j][3] * 0.125f : -1e30f;
            }
            // row max (rows r0, r0+8) across 4 lanes of the quad
            float mx0 = -1e30f, mx1 = -1e30f;
#pragma unroll
            for (int j = 0; j < 8; j++) {
                mx0 = fmaxf(mx0, fmaxf(sacc[j][0], sacc[j][1]));
                mx1 = fmaxf(mx1, fmaxf(sacc[j][2], sacc[j][3]));
            }
            mx0 = fmaxf(mx0, __shfl_xor_sync(0xffffffffu, mx0, 1));
            mx0 = fmaxf(mx0, __shfl_xor_sync(0xffffffffu, mx0, 2));
            mx1 = fmaxf(mx1, __shfl_xor_sync(0xffffffffu, mx1, 1));
            mx1 = fmaxf(mx1, __shfl_xor_sync(0xffffffffu, mx1, 2));
            float mn0 = fmaxf(mrow0, mx0), mn1 = fmaxf(mrow1, mx1);
            float al0 = __expf(mrow0 - mn0), al1 = __expf(mrow1 - mn1);
            mrow0 = mn0; mrow1 = mn1;

            uint32_t ph[8][2], pl[8][2];
            float ls0 = 0.f, ls1 = 0.f;
#pragma unroll
            for (int j = 0; j < 8; j++) {
                float p0 = __expf(sacc[j][0] - mn0);
                float p1 = __expf(sacc[j][1] - mn0);
                float p2 = __expf(sacc[j][2] - mn1);
                float p3 = __expf(sacc[j][3] - mn1);
                ls0 += p0 + p1; ls1 += p2 + p3;
                bf16 h0, l0, h1, l1, h2, l2, h3, l3;
                f2hilo(p0, h0, l0); f2hilo(p1, h1, l1);
                f2hilo(p2, h2, l2); f2hilo(p3, h3, l3);
                ph[j][0] = packbf(h0, h1); pl[j][0] = packbf(l0, l1);
                ph[j][1] = packbf(h2, h3); pl[j][1] = packbf(l2, l3);
            }
            ls0 += __shfl_xor_sync(0xffffffffu, ls0, 1);
            ls0 += __shfl_xor_sync(0xffffffffu, ls0, 2);
            ls1 += __shfl_xor_sync(0xffffffffu, ls1, 1);
            ls1 += __shfl_xor_sync(0xffffffffu, ls1, 2);
            lrow0 = lrow0 * al0 + ls0;
            lrow1 = lrow1 * al1 + ls1;
#pragma unroll
            for (int j = 0; j < 8; j++) {
                oacc[j][0] *= al0; oacc[j][1] *= al0;
                oacc[j][2] *= al1; oacc[j][3] *= al1;
            }
            // P @ V
#pragma unroll
            for (int pv = 0; pv < 4; pv++) {
#pragma unroll
                for (int s = 0; s < 4; s++) {
                    int tok = 16 * s + ((lane >> 3) & 1) * 8 + (lane & 7);
                    int dc  = 16 * pv + (lane >> 4) * 8;
                    uint32_t so = tok * 128 + ((((uint32_t)(dc >> 3)) ^ (uint32_t)(tok & 7)) << 4);
                    uint32_t v4h[4], v4l[4];
                    ldsm4t(v4h, base + 16384 + so);
                    ldsm4t(v4l, base + 24576 + so);
                    uint32_t pah[4] = {ph[2*s][0], ph[2*s][1], ph[2*s+1][0], ph[2*s+1][1]};
                    uint32_t pal[4] = {pl[2*s][0], pl[2*s][1], pl[2*s+1][0], pl[2*s+1][1]};
                    mma16816(oacc[2*pv],   pah, v4h[0], v4h[1]);
                    mma16816(oacc[2*pv+1], pah, v4h[2], v4h[3]);
                    mma16816(oacc[2*pv],   pah, v4l[0], v4l[1]);
                    mma16816(oacc[2*pv+1], pah, v4l[2], v4l[3]);
                    mma16816(oacc[2*pv],   pal, v4h[0], v4h[1]);
                    mma16816(oacc[2*pv+1], pal, v4h[2], v4h[3]);
                }
            }
        }
        __syncthreads();
        if (kb + 1 < nkb) {
            if (kb + 2 < nkb) { load_kv(kb & 1, kb + 2); cp_commit(); cp_wait<1>(); }
            else cp_wait<0>();
            __syncthreads();
        }
    }

    // normalize + write O (split bf16)
    float rl0 = 1.f / lrow0, rl1 = 1.f / lrow1;
    size_t ob0 = (tb + r0) * (size_t)DMODEL + h * HDIM + 2 * (lane & 3);
    size_t ob1 = ob0 + 8 * (size_t)DMODEL;
#pragma unroll
    for (int j = 0; j < 8; j++) {
        float o0 = oacc[j][0] * rl0, o1 = oacc[j][1] * rl0;
        float o2 = oacc[j][2] * rl1, o3 = oacc[j][3] * rl1;
        bf16 h0, l0, h1, l1, h2, l2, h3, l3;
        f2hilo(o0, h0, l0); f2hilo(o1, h1, l1);
        f2hilo(o2, h2, l2); f2hilo(o3, h3, l3);
        *(uint32_t*)(oh + ob0 + 8 * j) = packbf(h0, h1);
        *(uint32_t*)(ol + ob0 + 8 * j) = packbf(l0, l1);
        *(uint32_t*)(oh + ob1 + 8 * j) = packbf(h2, h3);
        *(uint32_t*)(ol + ob1 + 8 * j) = packbf(l2, l3);
    }
}

// ---------------- embedding ----------------
__global__ void embed_kernel(const int* __restrict__ idx,
                             const float* __restrict__ tok,
                             const float* __restrict__ pos,
                             float* __restrict__ x)
{
    int t = blockIdx.x;
    int token = idx[t];
    const float* tr = tok + (size_t)token * DMODEL;
    const float* pr = pos + (size_t)(t & (TSEQ - 1)) * DMODEL;
    float* xr = x + (size_t)t * DMODEL;
    for (int d = threadIdx.x; d < DMODEL; d += blockDim.x)
        xr[d] = tr[d] + pr[d];
}

// ---------------- layernorm: fp32 in, (hi,lo) bf16 out ----------------
__global__ __launch_bounds__(256) void layernorm_kernel(
    const float* __restrict__ x, bf16* __restrict__ yh, bf16* __restrict__ yl,
    const float* __restrict__ w, const float* __restrict__ bvec)
{
    __shared__ float sh1[32], sh2[32];
    int row = blockIdx.x;
    const float* px = x + (size_t)row * DMODEL;
    int tid = threadIdx.x;
    int lane = tid & 31, wid = tid >> 5;

    float v[4];
    float s = 0.f, ss = 0.f;
#pragma unroll
    for (int c = 0; c < 4; c++) {
        v[c] = px[tid + c * 256];
        s += v[c];
        ss = fmaf(v[c], v[c], ss);
    }
#pragma unroll
    for (int o = 16; o; o >>= 1) {
        s  += __shfl_xor_sync(0xffffffffu, s,  o);
        ss += __shfl_xor_sync(0xffffffffu, ss, o);
    }
    if (lane == 0) { sh1[wid] = s; sh2[wid] = ss; }
    __syncthreads();
    if (tid < 32) {
        s  = (tid < 8) ? sh1[tid] : 0.f;
        ss = (tid < 8) ? sh2[tid] : 0.f;
#pragma unroll
        for (int o = 4; o; o >>= 1) {
            s  += __shfl_xor_sync(0xffffffffu, s,  o);
            ss += __shfl_xor_sync(0xffffffffu, ss, o);
        }
        if (tid == 0) { sh1[0] = s; sh2[0] = ss; }
    }
    __syncthreads();
    s = sh1[0]; ss = sh2[0];
    float mean = s * (1.f / DMODEL);
    float var  = ss * (1.f / DMODEL) - mean * mean;
    float inv  = rsqrtf(var + 1e-5f);
#pragma unroll
    for (int c = 0; c < 4; c++) {
        int j = tid + c * 256;
        float y = (v[c] - mean) * inv * w[j] + bvec[j];
        bf16 hh, ll;
        f2hilo(y, hh, ll);
        yh[(size_t)row * DMODEL + j] = hh;
        yl[(size_t)row * DMODEL + j] = ll;
    }
}

// ---------------- launch ----------------
extern "C" void kernel_launch(void* const* d_in, const int* in_sizes, int n_in,
                              void* d_out, int out_size)
{
    (void)in_sizes; (void)n_in; (void)out_size;
    const int*   idx     = (const int*)  d_in[0];
    const float* tok_emb = (const float*)d_in[1];
    const float* pos_emb = (const float*)d_in[2];
    const float* ln1_w   = (const float*)d_in[3];
    const float* ln1_b   = (const float*)d_in[4];
    const float* qkv_w   = (const float*)d_in[5];
    const float* out_w   = (const float*)d_in[6];
    const float* ln2_w   = (const float*)d_in[7];
    const float* ln2_b   = (const float*)d_in[8];
    const float* ffn1_w  = (const float*)d_in[9];
    const float* ffn2_w  = (const float*)d_in[10];
    const float* lnf_w   = (const float*)d_in[11];
    const float* lnf_b   = (const float*)d_in[12];
    float* out = (float*)d_out;

    float *x;
    bf16 *hh, *hl, *qvh, *qvl, *oh, *ol, *fh, *fl;
    bf16 *wqh, *wql, *woh, *wol, *w1h, *w1l, *w2h, *w2l, *eh, *el;
    cudaGetSymbolAddress((void**)&x,    g_x);
    cudaGetSymbolAddress((void**)&hh,   g_hh);   cudaGetSymbolAddress((void**)&hl,  g_hl);
    cudaGetSymbolAddress((void**)&qvh,  g_qkvh); cudaGetSymbolAddress((void**)&qvl, g_qkvl);
    cudaGetSymbolAddress((void**)&oh,   g_oh);   cudaGetSymbolAddress((void**)&ol,  g_ol);
    cudaGetSymbolAddress((void**)&fh,   g_fh);   cudaGetSymbolAddress((void**)&fl,  g_fl);
    cudaGetSymbolAddress((void**)&wqh,  g_wqh);  cudaGetSymbolAddress((void**)&wql, g_wql);
    cudaGetSymbolAddress((void**)&woh,  g_woh);  cudaGetSymbolAddress((void**)&wol, g_wol);
    cudaGetSymbolAddress((void**)&w1h,  g_w1h);  cudaGetSymbolAddress((void**)&w1l, g_w1l);
    cudaGetSymbolAddress((void**)&w2h,  g_w2h);  cudaGetSymbolAddress((void**)&w2l, g_w2l);
    cudaGetSymbolAddress((void**)&eh,   g_eh);   cudaGetSymbolAddress((void**)&el,  g_el);

    cudaFuncSetAttribute(gemm_bf16x2<EPI_STORE>, cudaFuncAttributeMaxDynamicSharedMemorySize, 65536);
    cudaFuncSetAttribute(gemm_bf16x2<EPI_ADD>,   cudaFuncAttributeMaxDynamicSharedMemorySize, 65536);
    cudaFuncSetAttribute(gemm_bf16x2<EPI_GELU>,  cudaFuncAttributeMaxDynamicSharedMemorySize, 65536);
    cudaFuncSetAttribute(gemm_bf16x2<EPI_HILO>,  cudaFuncAttributeMaxDynamicSharedMemorySize, 65536);
    cudaFuncSetAttribute(flash_kernel,           cudaFuncAttributeMaxDynamicSharedMemorySize, 98304);

    // weight / embedding split to (hi, lo) bf16
    {
        int n;
        n = NL*3*DMODEL*DMODEL; cvt_hilo<<<n/1024, 256>>>(qkv_w,  wqh, wql, n);
        n = NL*DMODEL*DMODEL;   cvt_hilo<<<n/1024, 256>>>(out_w,  woh, wol, n);
        n = NL*DFF*DMODEL;      cvt_hilo<<<n/1024, 256>>>(ffn1_w, w1h, w1l, n);
        n = NL*DMODEL*DFF;      cvt_hilo<<<n/1024, 256>>>(ffn2_w, w2h, w2l, n);
        n = VOC*DMODEL;         cvt_hilo<<<n/1024, 256>>>(tok_emb, eh, el, n);
    }

    embed_kernel<<<MTOK, 256>>>(idx, tok_emb, pos_emb, x);

    for (int l = 0; l < NL; l++) {
        // --- attention block ---
        layernorm_kernel<<<MTOK, 256>>>(x, hh, hl, ln1_w + l * DMODEL, ln1_b + l * DMODEL);
        gemm_bf16x2<EPI_HILO><<<dim3(3*DMODEL/128, MTOK/128), 256, 65536>>>(
            hh, hl, wqh + (size_t)l*3*DMODEL*DMODEL, wql + (size_t)l*3*DMODEL*DMODEL,
            nullptr, qvh, qvl, MTOK, 3*DMODEL, DMODEL);
        flash_kernel<<<dim3(TSEQ/128, BATCH*NH), 256, 98304>>>(qvh, qvl, oh, ol);
        gemm_bf16x2<EPI_ADD><<<dim3(DMODEL/128, MTOK/128), 256, 65536>>>(
            oh, ol, woh + (size_t)l*DMODEL*DMODEL, wol + (size_t)l*DMODEL*DMODEL,
            x, nullptr, nullptr, MTOK, DMODEL, DMODEL);
        // --- FFN block ---
        layernorm_kernel<<<MTOK, 256>>>(x, hh, hl, ln2_w + l * DMODEL, ln2_b + l * DMODEL);
        gemm_bf16x2<EPI_GELU><<<dim3(DFF/128, MTOK/128), 256, 65536>>>(
            hh, hl, w1h + (size_t)l*DFF*DMODEL, w1l + (size_t)l*DFF*DMODEL,
            nullptr, fh, fl, MTOK, DFF, DMODEL);
        gemm_bf16x2<EPI_ADD><<<dim3(DMODEL/128, MTOK/128), 256, 65536>>>(
            fh, fl, w2h + (size_t)l*DMODEL*DFF, w2l + (size_t)l*DMODEL*DFF,
            x, nullptr, nullptr, MTOK, DMODEL, DFF);
    }

    layernorm_kernel<<<MTOK, 256>>>(x, hh, hl, lnf_w, lnf_b);
    gemm_bf16x2<EPI_STORE><<<dim3(VOC/128, MTOK/128), 256, 65536>>>(
        hh, hl, eh, el, out, nullptr, nullptr, MTOK, VOC, DMODEL);
}

// round 5
// speedup vs baseline: 3.4804x; 1.1900x over previous
#include <cuda_runtime.h>
#include <cuda_fp16.h>
#include <math.h>
#include <stdint.h>

// ---------------- problem constants ----------------
#define NL     6
#define DMODEL 1024
#define DFF    4096
#define VOC    32000
#define NH     16
#define HDIM   64
#define BATCH  2
#define TSEQ   1024
#define MTOK   (BATCH*TSEQ)   // 2048

// ---------------- scratch (static device globals; no allocation) ----------------
__device__ float g_x[MTOK * DMODEL];

__device__ __align__(16) half g_h [MTOK * DMODEL];                 // LN output (single fp16)
__device__ __align__(16) half g_qkvh[(size_t)MTOK * 3 * DMODEL], g_qkvl[(size_t)MTOK * 3 * DMODEL];
__device__ __align__(16) half g_o [MTOK * DMODEL];                 // attention O (single fp16)
__device__ __align__(16) half g_f [(size_t)MTOK * DFF];            // FFN mid (single fp16)

__device__ __align__(16) half g_wqh[(size_t)NL*3*DMODEL*DMODEL], g_wql[(size_t)NL*3*DMODEL*DMODEL];
__device__ __align__(16) half g_woh[(size_t)NL*DMODEL*DMODEL],   g_wol[(size_t)NL*DMODEL*DMODEL];
__device__ __align__(16) half g_w1h[(size_t)NL*DFF*DMODEL],      g_w1l[(size_t)NL*DFF*DMODEL];
__device__ __align__(16) half g_w2h[(size_t)NL*DMODEL*DFF],      g_w2l[(size_t)NL*DMODEL*DFF];
__device__ __align__(16) half g_eh [(size_t)VOC*DMODEL],         g_el [(size_t)VOC*DMODEL];

// ---------------- helpers ----------------
__device__ __forceinline__ void f2hilo(float x, half& h, half& l) {
    h = __float2half(x);
    l = __float2half(x - __half2float(h));
}
__device__ __forceinline__ uint32_t packh(half a, half b) {
    __half2 t; t.x = a; t.y = b;
    return *(uint32_t*)&t;
}

__device__ __forceinline__ void cp_async16(uint32_t s, const void* g) {
    asm volatile("cp.async.cg.shared.global [%0], [%1], 16;\n" :: "r"(s), "l"(g));
}
__device__ __forceinline__ void cp_commit() { asm volatile("cp.async.commit_group;\n"); }
template<int N> __device__ __forceinline__ void cp_wait() {
    asm volatile("cp.async.wait_group %0;\n" :: "n"(N));
}

__device__ __forceinline__ void ldsm4(uint32_t* r, uint32_t addr) {
    asm volatile("ldmatrix.sync.aligned.m8n8.x4.shared.b16 {%0,%1,%2,%3}, [%4];\n"
        : "=r"(r[0]), "=r"(r[1]), "=r"(r[2]), "=r"(r[3]) : "r"(addr));
}
__device__ __forceinline__ void ldsm4t(uint32_t* r, uint32_t addr) {
    asm volatile("ldmatrix.sync.aligned.m8n8.x4.trans.shared.b16 {%0,%1,%2,%3}, [%4];\n"
        : "=r"(r[0]), "=r"(r[1]), "=r"(r[2]), "=r"(r[3]) : "r"(addr));
}

__device__ __forceinline__ void mma16816(float* c, const uint32_t* a, uint32_t b0, uint32_t b1) {
    asm volatile(
        "mma.sync.aligned.m16n8k16.row.col.f32.f16.f16.f32 "
        "{%0,%1,%2,%3}, {%4,%5,%6,%7}, {%8,%9}, {%0,%1,%2,%3};\n"
        : "+f"(c[0]), "+f"(c[1]), "+f"(c[2]), "+f"(c[3])
        : "r"(a[0]), "r"(a[1]), "r"(a[2]), "r"(a[3]), "r"(b0), "r"(b1));
}

// ---------------- fp32 -> (hi,lo) fp16 conversion ----------------
__global__ __launch_bounds__(256) void cvt_hilo(const float* __restrict__ x,
                                                half* __restrict__ h, half* __restrict__ l,
                                                int n)
{
    int i = (blockIdx.x * 256 + threadIdx.x) * 4;
    if (i >= n) return;
    float4 v = *(const float4*)(x + i);
    half h0, h1, h2, h3, l0, l1, l2, l3;
    f2hilo(v.x, h0, l0); f2hilo(v.y, h1, l1);
    f2hilo(v.z, h2, l2); f2hilo(v.w, h3, l3);
    *(uint32_t*)(h + i)     = packh(h0, h1);
    *(uint32_t*)(h + i + 2) = packh(h2, h3);
    *(uint32_t*)(l + i)     = packh(l0, l1);
    *(uint32_t*)(l + i + 2) = packh(l2, l3);
}

// ---------------- fp16 2-term GEMM (mma.sync) ----------------
// C[M,N] = A[M,K] * (Bh+Bl)[N,K]^T   (A single fp16, weights split)
// 128x128 block, BK=32, 256 threads (8 warps, 2x4), warp tile 64x32.
#define EPI_STORE 0
#define EPI_ADD   1
#define EPI_GELU  2
#define EPI_HILO  3

template<int EPI>
__global__ __launch_bounds__(256) void gemm_f16(
    const half* __restrict__ A,
    const half* __restrict__ Bh, const half* __restrict__ Bl,
    float* __restrict__ C, half* __restrict__ Ch, half* __restrict__ Cl,
    int M, int N, int K)
{
    extern __shared__ uint8_t smem[];
    const uint32_t smem_u32 = (uint32_t)__cvta_generic_to_shared(smem);
    // stage(2) x [A 8KB | Bh 8KB | Bl 8KB]

    const int tid  = threadIdx.x;
    const int lane = tid & 31;
    const int wid  = tid >> 5;
    const int wm   = wid & 1;
    const int wn   = wid >> 1;
    const int bm   = blockIdx.y * 128;
    const int bn   = blockIdx.x * 128;

    const half* Ab  = A  + (size_t)bm * K;
    const half* Bhb = Bh + (size_t)bn * K;
    const half* Blb = Bl + (size_t)bn * K;

    float acc[4][4][4];
#pragma unroll
    for (int a = 0; a < 4; a++)
#pragma unroll
        for (int b = 0; b < 4; b++)
#pragma unroll
            for (int c = 0; c < 4; c++) acc[a][b][c] = 0.f;

    const int ntiles = K >> 5;

    auto load_stage = [&](int st, int k0) {
        uint32_t base = smem_u32 + st * 24576;
#pragma unroll
        for (int i = 0; i < 2; i++) {
            int idx = tid * 2 + i;          // 0..511
            int r = idx >> 2, c = idx & 3;
            size_t go = (size_t)r * K + k0 + c * 8;
            uint32_t so = base + r * 64 + (((uint32_t)(c ^ (r & 3))) << 4);
            cp_async16(so,          Ab  + go);
            cp_async16(so + 8192,   Bhb + go);
            cp_async16(so + 16384,  Blb + go);
        }
    };

    load_stage(0, 0);
    cp_commit();

    for (int t = 0; t < ntiles; t++) {
        if (t + 1 < ntiles) {
            load_stage((t + 1) & 1, (t + 1) << 5);
            cp_commit();
            cp_wait<1>();
        } else {
            cp_wait<0>();
        }
        __syncthreads();

        const uint32_t bA  = smem_u32 + (t & 1) * 24576;
        const uint32_t bBh = bA + 8192;
        const uint32_t bBl = bA + 16384;

#pragma unroll
        for (int s = 0; s < 2; s++) {
            uint32_t af[4][4];
#pragma unroll
            for (int mt = 0; mt < 4; mt++) {
                int row = wm * 64 + mt * 16 + (lane & 15);
                int ch  = 2 * s + (lane >> 4);
                uint32_t off = row * 64 + (((uint32_t)(ch ^ (row & 3))) << 4);
                ldsm4(af[mt], bA + off);
            }
            uint32_t bh[2][4], bl[2][4];
#pragma unroll
            for (int p = 0; p < 2; p++) {
                int row = wn * 32 + p * 16 + (lane & 15);
                int ch  = 2 * s + (lane >> 4);
                uint32_t off = row * 64 + (((uint32_t)(ch ^ (row & 3))) << 4);
                ldsm4(bh[p], bBh + off);
                ldsm4(bl[p], bBl + off);
            }
            // 2 waves of 16 independent MMAs
#pragma unroll
            for (int mt = 0; mt < 4; mt++)
#pragma unroll
                for (int nt = 0; nt < 4; nt++) {
                    int p = nt >> 1, q = nt & 1;
                    mma16816(acc[mt][nt], af[mt], bh[p][q], bh[p][q + 2]);
                }
#pragma unroll
            for (int mt = 0; mt < 4; mt++)
#pragma unroll
                for (int nt = 0; nt < 4; nt++) {
                    int p = nt >> 1, q = nt & 1;
                    mma16816(acc[mt][nt], af[mt], bl[p][q], bl[p][q + 2]);
                }
        }
        __syncthreads();
    }

    // --- epilogue ---
#pragma unroll
    for (int mt = 0; mt < 4; mt++) {
#pragma unroll
        for (int nt = 0; nt < 4; nt++) {
            int row = bm + wm * 64 + mt * 16 + (lane >> 2);
            int col = bn + wn * 32 + nt * 8 + (lane & 3) * 2;
            size_t i0 = (size_t)row * N + col;
            size_t i1 = i0 + (size_t)8 * N;
            float* c = acc[mt][nt];
            if (EPI == EPI_STORE) {
                *(float2*)(C + i0) = make_float2(c[0], c[1]);
                *(float2*)(C + i1) = make_float2(c[2], c[3]);
            } else if (EPI == EPI_ADD) {
                C[i0]   += c[0]; C[i0+1] += c[1];
                C[i1]   += c[2]; C[i1+1] += c[3];
            } else if (EPI == EPI_GELU) {
#pragma unroll
                for (int e = 0; e < 4; e += 2) {
                    size_t ii = (e == 0) ? i0 : i1;
                    float v0 = c[e], v1 = c[e+1];
                    float q0 = 0.5f * v0 * (1.f + erff(v0 * 0.70710678118654752f));
                    float q1 = 0.5f * v1 * (1.f + erff(v1 * 0.70710678118654752f));
                    *(uint32_t*)(Ch + ii) = packh(__float2half(q0), __float2half(q1));
                }
            } else {  // EPI_HILO (for QKV -> flash)
#pragma unroll
                for (int e = 0; e < 4; e += 2) {
                    size_t ii = (e == 0) ? i0 : i1;
                    half h0, l0, h1, l1;
                    f2hilo(c[e], h0, l0); f2hilo(c[e+1], h1, l1);
                    *(uint32_t*)(Ch + ii) = packh(h0, h1);
                    *(uint32_t*)(Cl + ii) = packh(l0, l1);
                }
            }
        }
    }
}

// ---------------- flash attention (split-fp16 mma.sync) ----------------
// q-tile 128 (8 warps x 16 rows), key blocks of 64, online softmax.
__global__ __launch_bounds__(256) void flash_kernel(
    const half* __restrict__ qkvh, const half* __restrict__ qkvl,
    half* __restrict__ o)
{
    extern __shared__ uint8_t fsm[];
    const uint32_t sb  = (uint32_t)__cvta_generic_to_shared(fsm);
    const uint32_t sQh = sb, sQl = sb + 16384;
    const uint32_t sKV = sb + 32768;   // + stage*32768 : [Kh|Kl|Vh|Vl] 8KB each

    const int tid = threadIdx.x, lane = tid & 31, w = tid >> 5;
    const int qi = (int)gridDim.x - 1 - (int)blockIdx.x;   // big tiles first
    const int bh = blockIdx.y;
    const int b = bh >> 4, h = bh & 15;
    const int qbase = qi * 128;
    const int nkb = (qbase + 128) >> 6;

    const size_t tb = (size_t)b * TSEQ;
    const half* Qh_ = qkvh + tb * 3 * DMODEL + h * HDIM;
    const half* Ql_ = qkvl + tb * 3 * DMODEL + h * HDIM;
    const half* Kh_ = Qh_ + DMODEL;
    const half* Kl_ = Ql_ + DMODEL;
    const half* Vh_ = Qh_ + 2 * DMODEL;
    const half* Vl_ = Ql_ + 2 * DMODEL;

    auto load_kv = [&](int buf, int kb) {
        uint32_t base = sKV + (uint32_t)buf * 32768;
#pragma unroll
        for (int i = 0; i < 2; i++) {
            int idx = tid * 2 + i;          // 0..511
            int r = idx >> 3, c = idx & 7;
            size_t go = (size_t)(kb * 64 + r) * 3 * DMODEL + c * 8;
            uint32_t so = r * 128 + (((uint32_t)(c ^ (r & 7))) << 4);
            cp_async16(base + so,         Kh_ + go);
            cp_async16(base + 8192 + so,  Kl_ + go);
            cp_async16(base + 16384 + so, Vh_ + go);
            cp_async16(base + 24576 + so, Vl_ + go);
        }
    };

#pragma unroll
    for (int i = 0; i < 4; i++) {
        int idx = tid * 4 + i;              // 0..1023
        int r = idx >> 3, c = idx & 7;
        size_t go = (size_t)(qbase + r) * 3 * DMODEL + c * 8;
        uint32_t so = r * 128 + (((uint32_t)(c ^ (r & 7))) << 4);
        cp_async16(sQh + so, Qh_ + go);
        cp_async16(sQl + so, Ql_ + go);
    }
    load_kv(0, 0);
    cp_commit();
    if (nkb > 1) { load_kv(1, 1); cp_commit(); cp_wait<1>(); }
    else cp_wait<0>();
    __syncthreads();

    uint32_t qfh[4][4], qfl[4][4];
#pragma unroll
    for (int s = 0; s < 4; s++) {
        int r = 16 * w + (lane & 15);
        int c = 2 * s + (lane >> 4);
        uint32_t so = r * 128 + (((uint32_t)(c ^ (r & 7))) << 4);
        ldsm4(qfh[s], sQh + so);
        ldsm4(qfl[s], sQl + so);
    }

    float oacc[8][4];
#pragma unroll
    for (int j = 0; j < 8; j++)
#pragma unroll
        for (int c = 0; c < 4; c++) oacc[j][c] = 0.f;
    float mrow0 = -1e30f, mrow1 = -1e30f, lrow0 = 0.f, lrow1 = 0.f;
    const int r0 = qbase + 16 * w + (lane >> 2);

    for (int kb = 0; kb < nkb; kb++) {
        if (kb * 64 <= qbase + 16 * w + 15) {
            uint32_t base = sKV + (uint32_t)(kb & 1) * 32768;
            float sacc[8][4];
#pragma unroll
            for (int j = 0; j < 8; j++)
#pragma unroll
                for (int c = 0; c < 4; c++) sacc[j][c] = 0.f;

#pragma unroll
            for (int p = 0; p < 4; p++) {
                int rr = 16 * p + (lane & 15);
#pragma unroll
                for (int s = 0; s < 4; s++) {
                    int cc = 2 * s + (lane >> 4);
                    uint32_t so = rr * 128 + (((uint32_t)(cc ^ (rr & 7))) << 4);
                    uint32_t kh4[4], kl4[4];
                    ldsm4(kh4, base + so);
                    ldsm4(kl4, base + 8192 + so);
                    mma16816(sacc[2*p],   qfh[s], kh4[0], kh4[2]);
                    mma16816(sacc[2*p+1], qfh[s], kh4[1], kh4[3]);
                    mma16816(sacc[2*p],   qfh[s], kl4[0], kl4[2]);
                    mma16816(sacc[2*p+1], qfh[s], kl4[1], kl4[3]);
                    mma16816(sacc[2*p],   qfl[s], kh4[0], kh4[2]);
                    mma16816(sacc[2*p+1], qfl[s], kh4[1], kh4[3]);
                }
            }
            int cbase = kb * 64 + 2 * (lane & 3);
#pragma unroll
            for (int j = 0; j < 8; j++) {
                int c0 = cbase + 8 * j;
                sacc[j][0] = (c0     <= r0    ) ? sacc[j][0] * 0.125f : -1e30f;
                sacc[j][1] = (c0 + 1 <= r0    ) ? sacc[j][1] * 0.125f : -1e30f;
                sacc[j][2] = (c0     <= r0 + 8) ? sacc[j][2] * 0.125f : -1e30f;
                sacc[j][3] = (c0 + 1 <= r0 + 8) ? sacc[j][3] * 0.125f : -1e30f;
            }
            float mx0 = -1e30f, mx1 = -1e30f;
#pragma unroll
            for (int j = 0; j < 8; j++) {
                mx0 = fmaxf(mx0, fmaxf(sacc[j][0], sacc[j][1]));
                mx1 = fmaxf(mx1, fmaxf(sacc[j][2], sacc[j][3]));
            }
            mx0 = fmaxf(mx0, __shfl_xor_sync(0xffffffffu, mx0, 1));
            mx0 = fmaxf(mx0, __shfl_xor_sync(0xffffffffu, mx0, 2));
            mx1 = fmaxf(mx1, __shfl_xor_sync(0xffffffffu, mx1, 1));
            mx1 = fmaxf(mx1, __shfl_xor_sync(0xffffffffu, mx1, 2));
            float mn0 = fmaxf(mrow0, mx0), mn1 = fmaxf(mrow1, mx1);
            float al0 = __expf(mrow0 - mn0), al1 = __expf(mrow1 - mn1);
            mrow0 = mn0; mrow1 = mn1;

            uint32_t ph[8][2], pl[8][2];
            float ls0 = 0.f, ls1 = 0.f;
#pragma unroll
            for (int j = 0; j < 8; j++) {
                float p0 = __expf(sacc[j][0] - mn0);
                float p1 = __expf(sacc[j][1] - mn0);
                float p2 = __expf(sacc[j][2] - mn1);
                float p3 = __expf(sacc[j][3] - mn1);
                ls0 += p0 + p1; ls1 += p2 + p3;
                half h0, l0, h1, l1, h2, l2, h3, l3;
                f2hilo(p0, h0, l0); f2hilo(p1, h1, l1);
                f2hilo(p2, h2, l2); f2hilo(p3, h3, l3);
                ph[j][0] = packh(h0, h1); pl[j][0] = packh(l0, l1);
                ph[j][1] = packh(h2, h3); pl[j][1] = packh(l2, l3);
            }
            ls0 += __shfl_xor_sync(0xffffffffu, ls0, 1);
            ls0 += __shfl_xor_sync(0xffffffffu, ls0, 2);
            ls1 += __shfl_xor_sync(0xffffffffu, ls1, 1);
            ls1 += __shfl_xor_sync(0xffffffffu, ls1, 2);
            lrow0 = lrow0 * al0 + ls0;
            lrow1 = lrow1 * al1 + ls1;
#pragma unroll
            for (int j = 0; j < 8; j++) {
                oacc[j][0] *= al0; oacc[j][1] *= al0;
                oacc[j][2] *= al1; oacc[j][3] *= al1;
            }
#pragma unroll
            for (int pv = 0; pv < 4; pv++) {
#pragma unroll
                for (int s = 0; s < 4; s++) {
                    int tok = 16 * s + ((lane >> 3) & 1) * 8 + (lane & 7);
                    int dc  = 16 * pv + (lane >> 4) * 8;
                    uint32_t so = tok * 128 + ((((uint32_t)(dc >> 3)) ^ (uint32_t)(tok & 7)) << 4);
                    uint32_t v4h[4], v4l[4];
                    ldsm4t(v4h, base + 16384 + so);
                    ldsm4t(v4l, base + 24576 + so);
                    uint32_t pah[4] = {ph[2*s][0], ph[2*s][1], ph[2*s+1][0], ph[2*s+1][1]};
                    uint32_t pal[4] = {pl[2*s][0], pl[2*s][1], pl[2*s+1][0], pl[2*s+1][1]};
                    mma16816(oacc[2*pv],   pah, v4h[0], v4h[1]);
                    mma16816(oacc[2*pv+1], pah, v4h[2], v4h[3]);
                    mma16816(oacc[2*pv],   pah, v4l[0], v4l[1]);
                    mma16816(oacc[2*pv+1], pah, v4l[2], v4l[3]);
                    mma16816(oacc[2*pv],   pal, v4h[0], v4h[1]);
                    mma16816(oacc[2*pv+1], pal, v4h[2], v4h[3]);
                }
            }
        }
        __syncthreads();
        if (kb + 1 < nkb) {
            if (kb + 2 < nkb) { load_kv(kb & 1, kb + 2); cp_commit(); cp_wait<1>(); }
            else cp_wait<0>();
            __syncthreads();
        }
    }

    // normalize + write O (single fp16)
    float rl0 = 1.f / lrow0, rl1 = 1.f / lrow1;
    size_t ob0 = (tb + r0) * (size_t)DMODEL + h * HDIM + 2 * (lane & 3);
    size_t ob1 = ob0 + 8 * (size_t)DMODEL;
#pragma unroll
    for (int j = 0; j < 8; j++) {
        *(uint32_t*)(o + ob0 + 8 * j) =
            packh(__float2half(oacc[j][0] * rl0), __float2half(oacc[j][1] * rl0));
        *(uint32_t*)(o + ob1 + 8 * j) =
            packh(__float2half(oacc[j][2] * rl1), __float2half(oacc[j][3] * rl1));
    }
}

// ---------------- embedding ----------------
__global__ void embed_kernel(const int* __restrict__ idx,
                             const float* __restrict__ tok,
                             const float* __restrict__ pos,
                             float* __restrict__ x)
{
    int t = blockIdx.x;
    int token = idx[t];
    const float* tr = tok + (size_t)token * DMODEL;
    const float* pr = pos + (size_t)(t & (TSEQ - 1)) * DMODEL;
    float* xr = x + (size_t)t * DMODEL;
    for (int d = threadIdx.x; d < DMODEL; d += blockDim.x)
        xr[d] = tr[d] + pr[d];
}

// ---------------- layernorm: fp32 in, single fp16 out ----------------
__global__ __launch_bounds__(256) void layernorm_kernel(
    const float* __restrict__ x, half* __restrict__ y,
    const float* __restrict__ w, const float* __restrict__ bvec)
{
    __shared__ float sh1[32], sh2[32];
    int row = blockIdx.x;
    const float* px = x + (size_t)row * DMODEL;
    int tid = threadIdx.x;
    int lane = tid & 31, wid = tid >> 5;

    float v[4];
    float s = 0.f, ss = 0.f;
#pragma unroll
    for (int c = 0; c < 4; c++) {
        v[c] = px[tid + c * 256];
        s += v[c];
        ss = fmaf(v[c], v[c], ss);
    }
#pragma unroll
    for (int o = 16; o; o >>= 1) {
        s  += __shfl_xor_sync(0xffffffffu, s,  o);
        ss += __shfl_xor_sync(0xffffffffu, ss, o);
    }
    if (lane == 0) { sh1[wid] = s; sh2[wid] = ss; }
    __syncthreads();
    if (tid < 32) {
        s  = (tid < 8) ? sh1[tid] : 0.f;
        ss = (tid < 8) ? sh2[tid] : 0.f;
#pragma unroll
        for (int o = 4; o; o >>= 1) {
            s  += __shfl_xor_sync(0xffffffffu, s,  o);
            ss += __shfl_xor_sync(0xffffffffu, ss, o);
        }
        if (tid == 0) { sh1[0] = s; sh2[0] = ss; }
    }
    __syncthreads();
    s = sh1[0]; ss = sh2[0];
    float mean = s * (1.f / DMODEL);
    float var  = ss * (1.f / DMODEL) - mean * mean;
    float inv  = rsqrtf(var + 1e-5f);
#pragma unroll
    for (int c = 0; c < 4; c++) {
        int j = tid + c * 256;
        float yv = (v[c] - mean) * inv * w[j] + bvec[j];
        y[(size_t)row * DMODEL + j] = __float2half(yv);
    }
}

// ---------------- launch ----------------
extern "C" void kernel_launch(void* const* d_in, const int* in_sizes, int n_in,
                              void* d_out, int out_size)
{
    (void)in_sizes; (void)n_in; (void)out_size;
    const int*   idx     = (const int*)  d_in[0];
    const float* tok_emb = (const float*)d_in[1];
    const float* pos_emb = (const float*)d_in[2];
    const float* ln1_w   = (const float*)d_in[3];
    const float* ln1_b   = (const float*)d_in[4];
    const float* qkv_w   = (const float*)d_in[5];
    const float* out_w   = (const float*)d_in[6];
    const float* ln2_w   = (const float*)d_in[7];
    const float* ln2_b   = (const float*)d_in[8];
    const float* ffn1_w  = (const float*)d_in[9];
    const float* ffn2_w  = (const float*)d_in[10];
    const float* lnf_w   = (const float*)d_in[11];
    const float* lnf_b   = (const float*)d_in[12];
    float* out = (float*)d_out;

    float *x;
    half *h, *qvh, *qvl, *o, *f;
    half *wqh, *wql, *woh, *wol, *w1h, *w1l, *w2h, *w2l, *eh, *el;
    cudaGetSymbolAddress((void**)&x,    g_x);
    cudaGetSymbolAddress((void**)&h,    g_h);
    cudaGetSymbolAddress((void**)&qvh,  g_qkvh); cudaGetSymbolAddress((void**)&qvl, g_qkvl);
    cudaGetSymbolAddress((void**)&o,    g_o);
    cudaGetSymbolAddress((void**)&f,    g_f);
    cudaGetSymbolAddress((void**)&wqh,  g_wqh);  cudaGetSymbolAddress((void**)&wql, g_wql);
    cudaGetSymbolAddress((void**)&woh,  g_woh);  cudaGetSymbolAddress((void**)&wol, g_wol);
    cudaGetSymbolAddress((void**)&w1h,  g_w1h);  cudaGetSymbolAddress((void**)&w1l, g_w1l);
    cudaGetSymbolAddress((void**)&w2h,  g_w2h);  cudaGetSymbolAddress((void**)&w2l, g_w2l);
    cudaGetSymbolAddress((void**)&eh,   g_eh);   cudaGetSymbolAddress((void**)&el,  g_el);

    cudaFuncSetAttribute(gemm_f16<EPI_STORE>, cudaFuncAttributeMaxDynamicSharedMemorySize, 49152);
    cudaFuncSetAttribute(gemm_f16<EPI_ADD>,   cudaFuncAttributeMaxDynamicSharedMemorySize, 49152);
    cudaFuncSetAttribute(gemm_f16<EPI_GELU>,  cudaFuncAttributeMaxDynamicSharedMemorySize, 49152);
    cudaFuncSetAttribute(gemm_f16<EPI_HILO>,  cudaFuncAttributeMaxDynamicSharedMemorySize, 49152);
    cudaFuncSetAttribute(flash_kernel,        cudaFuncAttributeMaxDynamicSharedMemorySize, 98304);

    // weight / embedding split to (hi, lo) fp16
    {
        int n;
        n = NL*3*DMODEL*DMODEL; cvt_hilo<<<n/1024, 256>>>(qkv_w,  wqh, wql, n);
        n = NL*DMODEL*DMODEL;   cvt_hilo<<<n/1024, 256>>>(out_w,  woh, wol, n);
        n = NL*DFF*DMODEL;      cvt_hilo<<<n/1024, 256>>>(ffn1_w, w1h, w1l, n);
        n = NL*DMODEL*DFF;      cvt_hilo<<<n/1024, 256>>>(ffn2_w, w2h, w2l, n);
        n = VOC*DMODEL;         cvt_hilo<<<n/1024, 256>>>(tok_emb, eh, el, n);
    }

    embed_kernel<<<MTOK, 256>>>(idx, tok_emb, pos_emb, x);

    for (int l = 0; l < NL; l++) {
        // --- attention block ---
        layernorm_kernel<<<MTOK, 256>>>(x, h, ln1_w + l * DMODEL, ln1_b + l * DMODEL);
        gemm_f16<EPI_HILO><<<dim3(3*DMODEL/128, MTOK/128), 256, 49152>>>(
            h, wqh + (size_t)l*3*DMODEL*DMODEL, wql + (size_t)l*3*DMODEL*DMODEL,
            nullptr, qvh, qvl, MTOK, 3*DMODEL, DMODEL);
        flash_kernel<<<dim3(TSEQ/128, BATCH*NH), 256, 98304>>>(qvh, qvl, o);
        gemm_f16<EPI_ADD><<<dim3(DMODEL/128, MTOK/128), 256, 49152>>>(
            o, woh + (size_t)l*DMODEL*DMODEL, wol + (size_t)l*DMODEL*DMODEL,
            x, nullptr, nullptr, MTOK, DMODEL, DMODEL);
        // --- FFN block ---
        layernorm_kernel<<<MTOK, 256>>>(x, h, ln2_w + l * DMODEL, ln2_b + l * DMODEL);
        gemm_f16<EPI_GELU><<<dim3(DFF/128, MTOK/128), 256, 49152>>>(
            h, w1h + (size_t)l*DFF*DMODEL, w1l + (size_t)l*DFF*DMODEL,
            nullptr, f, nullptr, MTOK, DFF, DMODEL);
        gemm_f16<EPI_ADD><<<dim3(DMODEL/128, MTOK/128), 256, 49152>>>(
            f, w2h + (size_t)l*DMODEL*DFF, w2l + (size_t)l*DMODEL*DFF,
            x, nullptr, nullptr, MTOK, DMODEL, DFF);
    }

    layernorm_kernel<<<MTOK, 256>>>(x, h, lnf_w, lnf_b);
    gemm_f16<EPI_STORE><<<dim3(VOC/128, MTOK/128), 256, 49152>>>(
        h, eh, el, out, nullptr, nullptr, MTOK, VOC, DMODEL);
}